// round 1
// baseline (speedup 1.0000x reference)
#include <cuda_runtime.h>
#include <cuda_bf16.h>
#include <math.h>

// Problem constants
constexpr int B = 2;
constexpr int H = 16;
constexpr int N = 2048;
constexpr int A = 128;           // head dim
constexpr int W = 2048;          // model width
constexpr int HD = H * A;        // 2048
constexpr int Mdim = B * N;      // 4096
constexpr int Kdim = W;          // 2048
constexpr int Ndim = HD;         // 2048

// Scratch (device globals — no allocation allowed)
__device__ float g_Q[B * H * N * A];
__device__ float g_K[B * H * N * A];
__device__ float g_V[B * H * N * A];
__device__ float g_AO[B * H * N * A];

// head-major index: m = b*N + n, k = h*A + a  ->  [b][h][n][a]
__device__ __forceinline__ size_t idx_head(int m, int k) {
    int b = m >> 11, n = m & 2047;
    int h = k >> 7,  a = k & 127;
    return ((((size_t)b * H + h) << 11) + n) * A + a;
}

// ---------------------------------------------------------------------------
// SGEMM: C[M,N] = A[M,K] @ B[N,K]^T  (both operands K-contiguous)
// 128x128 block tile, BK=16, 8x8 per-thread tile, register prefetch.
// GATHER_A: A is head-major [b][h][n][a] gathered by (m,k)
// SCATTER_C: C scattered to head-major by (m,n)
// ---------------------------------------------------------------------------
template <int GATHER_A, int SCATTER_C>
__global__ __launch_bounds__(256)
void sgemm_kernel(const float* __restrict__ Ag, const float* __restrict__ Bg,
                  float* __restrict__ Cg) {
    __shared__ float As[16][128];
    __shared__ float Bs[16][128];

    const int tid = threadIdx.x;
    const int tx = tid & 15;      // N dir
    const int ty = tid >> 4;      // M dir
    const int m0 = blockIdx.y * 128;
    const int n0 = blockIdx.x * 128;

    const int lrow = tid >> 1;          // 0..127
    const int lcol = (tid & 1) * 8;     // 0 or 8

    float a_reg[8], b_reg[8];
    float acc[8][8];
#pragma unroll
    for (int i = 0; i < 8; i++)
#pragma unroll
        for (int j = 0; j < 8; j++) acc[i][j] = 0.f;

    // preload k-tile 0 into registers
    {
        size_t abase = GATHER_A ? idx_head(m0 + lrow, lcol)
                                : (size_t)(m0 + lrow) * Kdim + lcol;
        size_t bbase = (size_t)(n0 + lrow) * Kdim + lcol;
#pragma unroll
        for (int i = 0; i < 8; i++) a_reg[i] = Ag[abase + i];
#pragma unroll
        for (int i = 0; i < 8; i++) b_reg[i] = Bg[bbase + i];
    }

    constexpr int NT = Kdim / 16;
    for (int kt = 0; kt < NT; kt++) {
        // commit prefetched regs to smem
#pragma unroll
        for (int i = 0; i < 8; i++) As[lcol + i][lrow] = a_reg[i];
#pragma unroll
        for (int i = 0; i < 8; i++) Bs[lcol + i][lrow] = b_reg[i];
        __syncthreads();

        // prefetch next tile (overlaps with compute below)
        if (kt + 1 < NT) {
            int k0 = (kt + 1) * 16;
            size_t abase = GATHER_A ? idx_head(m0 + lrow, k0 + lcol)
                                    : (size_t)(m0 + lrow) * Kdim + k0 + lcol;
            size_t bbase = (size_t)(n0 + lrow) * Kdim + k0 + lcol;
#pragma unroll
            for (int i = 0; i < 8; i++) a_reg[i] = Ag[abase + i];
#pragma unroll
            for (int i = 0; i < 8; i++) b_reg[i] = Bg[bbase + i];
        }

        // compute
#pragma unroll
        for (int kk = 0; kk < 16; kk++) {
            float a8[8], b8[8];
            *(float4*)&a8[0] = *(const float4*)&As[kk][ty * 8];
            *(float4*)&a8[4] = *(const float4*)&As[kk][ty * 8 + 4];
            *(float4*)&b8[0] = *(const float4*)&Bs[kk][tx * 8];
            *(float4*)&b8[4] = *(const float4*)&Bs[kk][tx * 8 + 4];
#pragma unroll
            for (int i = 0; i < 8; i++)
#pragma unroll
                for (int j = 0; j < 8; j++)
                    acc[i][j] = fmaf(a8[i], b8[j], acc[i][j]);
        }
        __syncthreads();
    }

    // epilogue
#pragma unroll
    for (int i = 0; i < 8; i++) {
        int m = m0 + ty * 8 + i;
#pragma unroll
        for (int j = 0; j < 8; j++) {
            int n = n0 + tx * 8 + j;
            size_t ci = SCATTER_C ? idx_head(m, n) : (size_t)m * Ndim + n;
            Cg[ci] = acc[i][j];
        }
    }
}

// ---------------------------------------------------------------------------
// RoPE (interleaved pairs) applied in place to Q and K, head-major layout.
// theta[n, pair i] = n * 10000^{-i/63}, matching linspace(0,1,64) endpoint.
// ---------------------------------------------------------------------------
__global__ void rope_kernel(float* __restrict__ Q, float* __restrict__ K) {
    int idx = blockIdx.x * blockDim.x + threadIdx.x;   // pair index, [0, B*H*N*64)
    int i = idx & 63;
    int npos = (idx >> 6) & 2047;
    float freq = __powf(10000.0f, -(float)i * (1.0f / 63.0f));
    float th = (float)npos * freq;
    float s, c;
    sincosf(th, &s, &c);
    size_t base = (size_t)idx * 2;

    float q0 = Q[base], q1 = Q[base + 1];
    Q[base]     = q0 * c - q1 * s;
    Q[base + 1] = q1 * c + q0 * s;

    float k0 = K[base], k1 = K[base + 1];
    K[base]     = k0 * c - k1 * s;
    K[base + 1] = k1 * c + k0 * s;
}

// ---------------------------------------------------------------------------
// Causal flash attention (fp32, online softmax).
// One block = one (bh, 64-query tile). 256 threads.
// Score phase: 4x4 register tiles over a 64x64 S tile.
// Softmax/PV phase: thread owns (query, 32-dim chunk).
// ---------------------------------------------------------------------------
constexpr int BQ = 64;
constexpr int QV_STRIDE = 132;   // padded row stride for Q/V tiles (float4-aligned)
constexpr int K_STRIDE  = 129;   // padded row stride for K tile (scalar, spread banks)
constexpr int S_STRIDE  = 65;

constexpr int SMEM_FLOATS = BQ * QV_STRIDE   /* Qs */
                          + BQ * K_STRIDE    /* Ks */
                          + BQ * QV_STRIDE   /* Vs */
                          + BQ * S_STRIDE;   /* S  */

__global__ __launch_bounds__(256)
void attn_kernel(const float* __restrict__ Q, const float* __restrict__ K,
                 const float* __restrict__ V, float* __restrict__ O) {
    extern __shared__ float sm[];
    float* Qs = sm;
    float* Ks = Qs + BQ * QV_STRIDE;
    float* Vs = Ks + BQ * K_STRIDE;
    float* S  = Vs + BQ * QV_STRIDE;

    const int bh = blockIdx.y;
    const int qt = gridDim.x - 1 - blockIdx.x;   // heavy tiles launch first
    const int q0 = qt * BQ;
    const int tid = threadIdx.x;

    const float* Qbase = Q + (size_t)bh * N * A;
    const float* Kbase = K + (size_t)bh * N * A;
    const float* Vbase = V + (size_t)bh * N * A;

    // load Q tile (64 x 128), float4
#pragma unroll
    for (int i = 0; i < 8; i++) {
        int idx = tid + i * 256;          // 0..2047 float4s
        int r = idx >> 5, c4 = idx & 31;
        float4 v = *(const float4*)(Qbase + (size_t)(q0 + r) * A + c4 * 4);
        *(float4*)(Qs + r * QV_STRIDE + c4 * 4) = v;
    }

    // score-phase mapping
    const int sy = tid >> 4;   // 0..15 -> query group of 4
    const int sx = tid & 15;   // 0..15 -> key group of 4
    // softmax/PV mapping
    const int qi = tid >> 2;          // 0..63
    const int d0 = (tid & 3) * 32;

    float m = -INFINITY, l = 0.f;
    float acc[32];
#pragma unroll
    for (int i = 0; i < 32; i++) acc[i] = 0.f;

    const float scale = 0.08838834764831845f;  // 1/sqrt(128)

    const int ntiles = qt + 1;
    for (int kt = 0; kt < ntiles; kt++) {
        const int k0 = kt * BQ;
        __syncthreads();   // protect Ks/Vs/S from previous iteration readers

        // load K tile (scalar) and V tile (float4)
#pragma unroll
        for (int i = 0; i < 32; i++) {
            int idx = tid + i * 256;       // 0..8191
            int r = idx >> 7, c = idx & 127;
            Ks[r * K_STRIDE + c] = Kbase[(size_t)(k0 + r) * A + c];
        }
#pragma unroll
        for (int i = 0; i < 8; i++) {
            int idx = tid + i * 256;
            int r = idx >> 5, c4 = idx & 31;
            *(float4*)(Vs + r * QV_STRIDE + c4 * 4) =
                *(const float4*)(Vbase + (size_t)(k0 + r) * A + c4 * 4);
        }
        __syncthreads();

        // scores: 4x4 per thread over 64x64 tile
        float s4[4][4];
#pragma unroll
        for (int i = 0; i < 4; i++)
#pragma unroll
            for (int j = 0; j < 4; j++) s4[i][j] = 0.f;

        const float* qp = Qs + (sy * 4) * QV_STRIDE;
        const float* kp = Ks + (sx * 4) * K_STRIDE;
#pragma unroll 4
        for (int k = 0; k < A; k++) {
            float a0 = qp[k];
            float a1 = qp[QV_STRIDE + k];
            float a2 = qp[2 * QV_STRIDE + k];
            float a3 = qp[3 * QV_STRIDE + k];
            float b0 = kp[k];
            float b1 = kp[K_STRIDE + k];
            float b2 = kp[2 * K_STRIDE + k];
            float b3 = kp[3 * K_STRIDE + k];
            s4[0][0] = fmaf(a0, b0, s4[0][0]); s4[0][1] = fmaf(a0, b1, s4[0][1]);
            s4[0][2] = fmaf(a0, b2, s4[0][2]); s4[0][3] = fmaf(a0, b3, s4[0][3]);
            s4[1][0] = fmaf(a1, b0, s4[1][0]); s4[1][1] = fmaf(a1, b1, s4[1][1]);
            s4[1][2] = fmaf(a1, b2, s4[1][2]); s4[1][3] = fmaf(a1, b3, s4[1][3]);
            s4[2][0] = fmaf(a2, b0, s4[2][0]); s4[2][1] = fmaf(a2, b1, s4[2][1]);
            s4[2][2] = fmaf(a2, b2, s4[2][2]); s4[2][3] = fmaf(a2, b3, s4[2][3]);
            s4[3][0] = fmaf(a3, b0, s4[3][0]); s4[3][1] = fmaf(a3, b1, s4[3][1]);
            s4[3][2] = fmaf(a3, b2, s4[3][2]); s4[3][3] = fmaf(a3, b3, s4[3][3]);
        }
        // scale + causal mask + store to S
#pragma unroll
        for (int i = 0; i < 4; i++) {
            int qq = q0 + sy * 4 + i;
#pragma unroll
            for (int j = 0; j < 4; j++) {
                int kk2 = k0 + sx * 4 + j;
                float v = s4[i][j] * scale;
                if (kk2 > qq) v = -1e30f;
                S[(sy * 4 + i) * S_STRIDE + sx * 4 + j] = v;
            }
        }
        __syncthreads();

        // online softmax + P@V  (4 threads per query, redundant row stats)
        const float* srow = S + qi * S_STRIDE;
        float mnew = m;
#pragma unroll 8
        for (int j = 0; j < BQ; j++) mnew = fmaxf(mnew, srow[j]);
        float corr = expf(m - mnew);
        m = mnew;
        l *= corr;
#pragma unroll
        for (int i = 0; i < 32; i++) acc[i] *= corr;

        for (int j = 0; j < BQ; j++) {
            float p = expf(srow[j] - mnew);
            l += p;
            const float4* vp = (const float4*)(Vs + j * QV_STRIDE + d0);
#pragma unroll
            for (int c = 0; c < 8; c++) {
                float4 vv = vp[c];
                acc[c * 4 + 0] = fmaf(p, vv.x, acc[c * 4 + 0]);
                acc[c * 4 + 1] = fmaf(p, vv.y, acc[c * 4 + 1]);
                acc[c * 4 + 2] = fmaf(p, vv.z, acc[c * 4 + 2]);
                acc[c * 4 + 3] = fmaf(p, vv.w, acc[c * 4 + 3]);
            }
        }
    }

    float inv = 1.f / l;
    float* op = O + ((size_t)bh * N + q0 + qi) * A + d0;
#pragma unroll
    for (int i = 0; i < 32; i++) op[i] = acc[i] * inv;
}

// ---------------------------------------------------------------------------
extern "C" void kernel_launch(void* const* d_in, const int* in_sizes, int n_in,
                              void* d_out, int out_size) {
    const float* q  = (const float*)d_in[0];
    const float* Wq = (const float*)d_in[1];
    const float* Wk = (const float*)d_in[2];
    const float* Wv = (const float*)d_in[3];
    const float* Wo = (const float*)d_in[4];
    float* out = (float*)d_out;

    float *Qp, *Kp, *Vp, *AOp;
    cudaGetSymbolAddress((void**)&Qp,  g_Q);
    cudaGetSymbolAddress((void**)&Kp,  g_K);
    cudaGetSymbolAddress((void**)&Vp,  g_V);
    cudaGetSymbolAddress((void**)&AOp, g_AO);

    dim3 gg(Ndim / 128, Mdim / 128);   // (16, 32)

    // QKV projections -> head-major scratch
    sgemm_kernel<0, 1><<<gg, 256>>>(q, Wq, Qp);
    sgemm_kernel<0, 1><<<gg, 256>>>(q, Wk, Kp);
    sgemm_kernel<0, 1><<<gg, 256>>>(q, Wv, Vp);

    // RoPE on Q and K
    int npairs = B * H * N * (A / 2);  // 4,194,304
    rope_kernel<<<npairs / 256, 256>>>(Qp, Kp);

    // causal flash attention
    size_t smem = (size_t)SMEM_FLOATS * sizeof(float);
    cudaFuncSetAttribute(attn_kernel, cudaFuncAttributeMaxDynamicSharedMemorySize,
                         (int)smem);
    attn_kernel<<<dim3(N / BQ, B * H), 256, smem>>>(Qp, Kp, Vp, AOp);

    // output projection (gather head-major A)
    sgemm_kernel<1, 0><<<gg, 256>>>(AOp, Wo, out);
}

// round 3
// speedup vs baseline: 1.5144x; 1.5144x over previous
#include <cuda_runtime.h>
#include <cstdint>
#include <math.h>

// Problem constants
constexpr int B = 2;
constexpr int H = 16;
constexpr int N = 2048;
constexpr int A = 128;           // head dim
constexpr int W = 2048;          // model width
constexpr int HD = H * A;        // 2048
constexpr int Mdim = B * N;      // 4096
constexpr int Kdim = W;          // 2048

// Scratch (device globals — no allocation allowed)
__device__ float g_qr [Mdim * Kdim];     // tf32-rounded q
__device__ float g_Wqr[HD * W];
__device__ float g_Wkr[HD * W];
__device__ float g_Wvr[HD * W];
__device__ float g_Wor[W * HD];
__device__ float g_Q  [B * H * N * A];   // head-major
__device__ float g_K  [B * H * N * A];
__device__ float g_V  [B * H * N * A];
__device__ float g_AO [Mdim * HD];       // [b*n, h*a], tf32-rounded

// ---------------------------------------------------------------------------
// tf32 round-to-nearest (unbiased; mma HW truncates, so pre-round inputs)
// ---------------------------------------------------------------------------
__device__ __forceinline__ float rna_tf32(float x) {
    uint32_t u;
    asm("cvt.rna.tf32.f32 %0, %1;" : "=r"(u) : "f"(x));
    return __uint_as_float(u);
}

__global__ void round_tf32_kernel(const float4* __restrict__ in,
                                  float4* __restrict__ out, int n4) {
    int i = blockIdx.x * blockDim.x + threadIdx.x;
    if (i >= n4) return;
    float4 v = in[i];
    v.x = rna_tf32(v.x); v.y = rna_tf32(v.y);
    v.z = rna_tf32(v.z); v.w = rna_tf32(v.w);
    out[i] = v;
}

// ---------------------------------------------------------------------------
// tf32 mma.sync GEMM: C[M,Nc] = A[M,K] @ B[Nc,K]^T   (both K-contiguous)
// CTA tile 128x128, BK=32. 8 warps as 4(m) x 2(n); warp tile 32x64.
// Smem tiles are staged in *fragment order* so compute loads are plain
// conflict-free lds.128 / lds.64 (no ldmatrix needed for tf32).
//   A frag (m16k8): reg = (r>=8) | ((c>=4)<<1), lane = (r&7)*4 + (c&3)
//   B frag (k8n8):  reg = (k>=4),               lane = n*4 + (k&3)
// SCATTER_C: write head-major [b][h][n][a] instead of row-major [m][n].
// ---------------------------------------------------------------------------
template <int SCATTER_C>
__global__ __launch_bounds__(256, 2)
void tf32_gemm(const float* __restrict__ Ag, const float* __restrict__ Bg,
               float* __restrict__ Cg) {
    __shared__ __align__(16) float As[4096];   // [mt(8)][ks(4)][lane(32)*4+reg]
    __shared__ __align__(16) float Bs[4096];   // [nt(16)][ks(4)][lane(32)*2+reg]

    const int tid  = threadIdx.x;
    const int lane = tid & 31;
    const int wid  = tid >> 5;
    const int wm   = wid & 3;       // warp m index (0..3) -> 32 rows each
    const int wn   = wid >> 2;      // warp n index (0..1) -> 64 cols each
    const int m0   = blockIdx.y * 128;
    const int n0   = blockIdx.x * 128;

    float c[2][8][4];
#pragma unroll
    for (int mi = 0; mi < 2; mi++)
#pragma unroll
        for (int ni = 0; ni < 8; ni++)
#pragma unroll
            for (int j = 0; j < 4; j++) c[mi][ni][j] = 0.f;

    float4 pa[4], pb[4];

    auto load_tile = [&](int kt) {
#pragma unroll
        for (int i = 0; i < 4; i++) {
            int idx = tid + i * 256;
            int row = idx >> 3, c4 = idx & 7;
            pa[i] = *(const float4*)(Ag + (size_t)(m0 + row) * Kdim + kt * 32 + c4 * 4);
            pb[i] = *(const float4*)(Bg + (size_t)(n0 + row) * Kdim + kt * 32 + c4 * 4);
        }
    };

    load_tile(0);

    constexpr int NKT = Kdim / 32;   // 64
    for (int kt = 0; kt < NKT; kt++) {
        // scatter prefetched regs into fragment-order smem
#pragma unroll
        for (int i = 0; i < 4; i++) {
            int idx = tid + i * 256;
            int row = idx >> 3, c4 = idx & 7;
            {   // A: element (row, k= c4*4 + e)
                int mt = row >> 4, r = row & 15, ks = c4 >> 1, hi = c4 & 1;
                int reg = ((r >> 3) & 1) | (hi << 1);
                float* ba = &As[(mt * 4 + ks) * 128 + (r & 7) * 16 + reg];
                ba[0] = pa[i].x; ba[4] = pa[i].y; ba[8] = pa[i].z; ba[12] = pa[i].w;
            }
            {   // B: element (nrow=row, k)
                int nt = row >> 3, g = row & 7, ks = c4 >> 1, reg = c4 & 1;
                float* bb = &Bs[(nt * 4 + ks) * 64 + g * 8 + reg];
                bb[0] = pb[i].x; bb[2] = pb[i].y; bb[4] = pb[i].z; bb[6] = pb[i].w;
            }
        }
        __syncthreads();

        if (kt + 1 < NKT) load_tile(kt + 1);

#pragma unroll
        for (int ks = 0; ks < 4; ks++) {
            uint32_t af[2][4];
#pragma unroll
            for (int mi = 0; mi < 2; mi++) {
                float4 t = *(const float4*)&As[((wm * 2 + mi) * 4 + ks) * 128 + lane * 4];
                af[mi][0] = __float_as_uint(t.x);
                af[mi][1] = __float_as_uint(t.y);
                af[mi][2] = __float_as_uint(t.z);
                af[mi][3] = __float_as_uint(t.w);
            }
#pragma unroll
            for (int ni = 0; ni < 8; ni++) {
                float2 tb = *(const float2*)&Bs[((wn * 8 + ni) * 4 + ks) * 64 + lane * 2];
                uint32_t b0 = __float_as_uint(tb.x), b1 = __float_as_uint(tb.y);
#pragma unroll
                for (int mi = 0; mi < 2; mi++) {
                    asm volatile(
                        "mma.sync.aligned.m16n8k8.row.col.f32.tf32.tf32.f32 "
                        "{%0,%1,%2,%3}, {%4,%5,%6,%7}, {%8,%9}, {%0,%1,%2,%3};"
                        : "+f"(c[mi][ni][0]), "+f"(c[mi][ni][1]),
                          "+f"(c[mi][ni][2]), "+f"(c[mi][ni][3])
                        : "r"(af[mi][0]), "r"(af[mi][1]), "r"(af[mi][2]), "r"(af[mi][3]),
                          "r"(b0), "r"(b1));
                }
            }
        }
        __syncthreads();
    }

    // epilogue: c0,c1 at (gid, 2*tig), c2,c3 at (gid+8, 2*tig)
    const int gid = lane >> 2, tig = lane & 3;
#pragma unroll
    for (int mi = 0; mi < 2; mi++) {
#pragma unroll
        for (int ni = 0; ni < 8; ni++) {
            int n = n0 + wn * 64 + ni * 8 + tig * 2;
#pragma unroll
            for (int half = 0; half < 2; half++) {
                int m = m0 + wm * 32 + mi * 16 + gid + half * 8;
                float2 v = make_float2(c[mi][ni][half * 2], c[mi][ni][half * 2 + 1]);
                size_t dst;
                if (SCATTER_C) {
                    int b2 = m >> 11, np = m & 2047, h2 = n >> 7, a0 = n & 127;
                    dst = ((((size_t)b2 * H + h2) * N) + np) * A + a0;
                } else {
                    dst = (size_t)m * 2048 + n;
                }
                *(float2*)(Cg + dst) = v;
            }
        }
    }
}

// ---------------------------------------------------------------------------
// RoPE (interleaved pairs), in place on Q and K (head-major layout).
// ---------------------------------------------------------------------------
__global__ void rope_kernel(float* __restrict__ Q, float* __restrict__ K) {
    int idx = blockIdx.x * blockDim.x + threadIdx.x;   // pair index
    int i = idx & 63;
    int npos = (idx >> 6) & 2047;
    float freq = __powf(10000.0f, -(float)i * (1.0f / 63.0f));
    float th = (float)npos * freq;
    float s, c;
    sincosf(th, &s, &c);
    size_t base = (size_t)idx * 2;

    float q0 = Q[base], q1 = Q[base + 1];
    Q[base]     = q0 * c - q1 * s;
    Q[base + 1] = q1 * c + q0 * s;

    float k0 = K[base], k1 = K[base + 1];
    K[base]     = k0 * c - k1 * s;
    K[base + 1] = k1 * c + k0 * s;
}

// ---------------------------------------------------------------------------
// Causal flash attention (fp32, online softmax). Output written to
// [b*n, h*a] layout, tf32-rounded for the Wo GEMM.
// ---------------------------------------------------------------------------
constexpr int BQ = 64;
constexpr int QV_STRIDE = 132;
constexpr int K_STRIDE  = 129;
constexpr int S_STRIDE  = 65;

constexpr int SMEM_FLOATS = BQ * QV_STRIDE + BQ * K_STRIDE
                          + BQ * QV_STRIDE + BQ * S_STRIDE;

__global__ __launch_bounds__(256)
void attn_kernel(const float* __restrict__ Q, const float* __restrict__ K,
                 const float* __restrict__ V, float* __restrict__ O) {
    extern __shared__ float sm[];
    float* Qs = sm;
    float* Ks = Qs + BQ * QV_STRIDE;
    float* Vs = Ks + BQ * K_STRIDE;
    float* S  = Vs + BQ * QV_STRIDE;

    const int bh = blockIdx.y;
    const int qt = gridDim.x - 1 - blockIdx.x;
    const int q0 = qt * BQ;
    const int tid = threadIdx.x;

    const float* Qbase = Q + (size_t)bh * N * A;
    const float* Kbase = K + (size_t)bh * N * A;
    const float* Vbase = V + (size_t)bh * N * A;

#pragma unroll
    for (int i = 0; i < 8; i++) {
        int idx = tid + i * 256;
        int r = idx >> 5, c4 = idx & 31;
        float4 v = *(const float4*)(Qbase + (size_t)(q0 + r) * A + c4 * 4);
        *(float4*)(Qs + r * QV_STRIDE + c4 * 4) = v;
    }

    const int sy = tid >> 4;
    const int sx = tid & 15;
    const int qi = tid >> 2;
    const int d0 = (tid & 3) * 32;

    float m = -INFINITY, l = 0.f;
    float acc[32];
#pragma unroll
    for (int i = 0; i < 32; i++) acc[i] = 0.f;

    const float scale = 0.08838834764831845f;

    const int ntiles = qt + 1;
    for (int kt = 0; kt < ntiles; kt++) {
        const int k0 = kt * BQ;
        __syncthreads();

#pragma unroll
        for (int i = 0; i < 32; i++) {
            int idx = tid + i * 256;
            int r = idx >> 7, c = idx & 127;
            Ks[r * K_STRIDE + c] = Kbase[(size_t)(k0 + r) * A + c];
        }
#pragma unroll
        for (int i = 0; i < 8; i++) {
            int idx = tid + i * 256;
            int r = idx >> 5, c4 = idx & 31;
            *(float4*)(Vs + r * QV_STRIDE + c4 * 4) =
                *(const float4*)(Vbase + (size_t)(k0 + r) * A + c4 * 4);
        }
        __syncthreads();

        float s4[4][4];
#pragma unroll
        for (int i = 0; i < 4; i++)
#pragma unroll
            for (int j = 0; j < 4; j++) s4[i][j] = 0.f;

        const float* qp = Qs + (sy * 4) * QV_STRIDE;
        const float* kp = Ks + (sx * 4) * K_STRIDE;
#pragma unroll 4
        for (int k = 0; k < A; k++) {
            float a0 = qp[k];
            float a1 = qp[QV_STRIDE + k];
            float a2 = qp[2 * QV_STRIDE + k];
            float a3 = qp[3 * QV_STRIDE + k];
            float b0 = kp[k];
            float b1 = kp[K_STRIDE + k];
            float b2 = kp[2 * K_STRIDE + k];
            float b3 = kp[3 * K_STRIDE + k];
            s4[0][0] = fmaf(a0, b0, s4[0][0]); s4[0][1] = fmaf(a0, b1, s4[0][1]);
            s4[0][2] = fmaf(a0, b2, s4[0][2]); s4[0][3] = fmaf(a0, b3, s4[0][3]);
            s4[1][0] = fmaf(a1, b0, s4[1][0]); s4[1][1] = fmaf(a1, b1, s4[1][1]);
            s4[1][2] = fmaf(a1, b2, s4[1][2]); s4[1][3] = fmaf(a1, b3, s4[1][3]);
            s4[2][0] = fmaf(a2, b0, s4[2][0]); s4[2][1] = fmaf(a2, b1, s4[2][1]);
            s4[2][2] = fmaf(a2, b2, s4[2][2]); s4[2][3] = fmaf(a2, b3, s4[2][3]);
            s4[3][0] = fmaf(a3, b0, s4[3][0]); s4[3][1] = fmaf(a3, b1, s4[3][1]);
            s4[3][2] = fmaf(a3, b2, s4[3][2]); s4[3][3] = fmaf(a3, b3, s4[3][3]);
        }
#pragma unroll
        for (int i = 0; i < 4; i++) {
            int qq = q0 + sy * 4 + i;
#pragma unroll
            for (int j = 0; j < 4; j++) {
                int kk2 = k0 + sx * 4 + j;
                float v = s4[i][j] * scale;
                if (kk2 > qq) v = -1e30f;
                S[(sy * 4 + i) * S_STRIDE + sx * 4 + j] = v;
            }
        }
        __syncthreads();

        const float* srow = S + qi * S_STRIDE;
        float mnew = m;
#pragma unroll 8
        for (int j = 0; j < BQ; j++) mnew = fmaxf(mnew, srow[j]);
        float corr = expf(m - mnew);
        m = mnew;
        l *= corr;
#pragma unroll
        for (int i = 0; i < 32; i++) acc[i] *= corr;

        for (int j = 0; j < BQ; j++) {
            float p = expf(srow[j] - mnew);
            l += p;
            const float4* vp = (const float4*)(Vs + j * QV_STRIDE + d0);
#pragma unroll
            for (int c2 = 0; c2 < 8; c2++) {
                float4 vv = vp[c2];
                acc[c2 * 4 + 0] = fmaf(p, vv.x, acc[c2 * 4 + 0]);
                acc[c2 * 4 + 1] = fmaf(p, vv.y, acc[c2 * 4 + 1]);
                acc[c2 * 4 + 2] = fmaf(p, vv.z, acc[c2 * 4 + 2]);
                acc[c2 * 4 + 3] = fmaf(p, vv.w, acc[c2 * 4 + 3]);
            }
        }
    }

    float inv = 1.f / l;
    int b2 = bh >> 4, h2 = bh & 15;
    float* op = O + ((size_t)(b2 * N + q0 + qi)) * HD + h2 * A + d0;
#pragma unroll
    for (int i = 0; i < 32; i++) op[i] = rna_tf32(acc[i] * inv);
}

// ---------------------------------------------------------------------------
extern "C" void kernel_launch(void* const* d_in, const int* in_sizes, int n_in,
                              void* d_out, int out_size) {
    const float* q  = (const float*)d_in[0];
    const float* Wq = (const float*)d_in[1];
    const float* Wk = (const float*)d_in[2];
    const float* Wv = (const float*)d_in[3];
    const float* Wo = (const float*)d_in[4];
    float* out = (float*)d_out;

    float *qr, *Wqr, *Wkr, *Wvr, *Wor, *Qp, *Kp, *Vp, *AOp;
    cudaGetSymbolAddress((void**)&qr,  g_qr);
    cudaGetSymbolAddress((void**)&Wqr, g_Wqr);
    cudaGetSymbolAddress((void**)&Wkr, g_Wkr);
    cudaGetSymbolAddress((void**)&Wvr, g_Wvr);
    cudaGetSymbolAddress((void**)&Wor, g_Wor);
    cudaGetSymbolAddress((void**)&Qp,  g_Q);
    cudaGetSymbolAddress((void**)&Kp,  g_K);
    cudaGetSymbolAddress((void**)&Vp,  g_V);
    cudaGetSymbolAddress((void**)&AOp, g_AO);

    // tf32 pre-rounding (round-to-nearest -> unbiased tensor MMA)
    {
        int n4q = Mdim * Kdim / 4;
        int n4w = HD * W / 4;
        round_tf32_kernel<<<n4q / 256, 256>>>((const float4*)q,  (float4*)qr,  n4q);
        round_tf32_kernel<<<n4w / 256, 256>>>((const float4*)Wq, (float4*)Wqr, n4w);
        round_tf32_kernel<<<n4w / 256, 256>>>((const float4*)Wk, (float4*)Wkr, n4w);
        round_tf32_kernel<<<n4w / 256, 256>>>((const float4*)Wv, (float4*)Wvr, n4w);
        round_tf32_kernel<<<n4w / 256, 256>>>((const float4*)Wo, (float4*)Wor, n4w);
    }

    cudaFuncSetAttribute(attn_kernel, cudaFuncAttributeMaxDynamicSharedMemorySize,
                         (int)(SMEM_FLOATS * sizeof(float)));

    dim3 gg(2048 / 128, Mdim / 128);   // (16, 32)

    // QKV projections -> head-major scratch (tensor-core tf32)
    tf32_gemm<1><<<gg, 256>>>(qr, Wqr, Qp);
    tf32_gemm<1><<<gg, 256>>>(qr, Wkr, Kp);
    tf32_gemm<1><<<gg, 256>>>(qr, Wvr, Vp);

    // RoPE on Q and K
    int npairs = B * H * N * (A / 2);
    rope_kernel<<<npairs / 256, 256>>>(Qp, Kp);

    // causal flash attention
    attn_kernel<<<dim3(N / BQ, B * H), 256, SMEM_FLOATS * sizeof(float)>>>(Qp, Kp, Vp, AOp);

    // output projection (row-major A — no gather needed)
    tf32_gemm<0><<<gg, 256>>>(AOp, Wor, out);
}

// round 4
// speedup vs baseline: 4.8902x; 3.2293x over previous
#include <cuda_runtime.h>
#include <cstdint>
#include <math.h>

// Problem constants
constexpr int B = 2;
constexpr int H = 16;
constexpr int N = 2048;
constexpr int A = 128;           // head dim
constexpr int W = 2048;          // model width
constexpr int HD = H * A;        // 2048
constexpr int Mdim = B * N;      // 4096
constexpr int Kdim = W;          // 2048

// Scratch (device globals — no allocation allowed)
__device__ float g_qr [Mdim * Kdim];     // tf32-rounded q
__device__ float g_Wqr[HD * W];
__device__ float g_Wkr[HD * W];
__device__ float g_Wvr[HD * W];
__device__ float g_Wor[W * HD];
__device__ float g_Q  [B * H * N * A];   // head-major
__device__ float g_K  [B * H * N * A];
__device__ float g_V  [B * H * N * A];
__device__ float g_AO [Mdim * HD];       // [b*n, h*a], tf32-rounded

// ---------------------------------------------------------------------------
// helpers
// ---------------------------------------------------------------------------
__device__ __forceinline__ float rna_tf32(float x) {
    uint32_t u;
    asm("cvt.rna.tf32.f32 %0, %1;" : "=r"(u) : "f"(x));
    return __uint_as_float(u);
}
__device__ __forceinline__ uint32_t rna_tf32_bits(float x) {
    uint32_t u;
    asm("cvt.rna.tf32.f32 %0, %1;" : "=r"(u) : "f"(x));
    return u;
}
__device__ __forceinline__ uint32_t smem_u32(const void* p) {
    uint32_t a;
    asm("{ .reg .u64 t; cvta.to.shared.u64 t, %1; cvt.u32.u64 %0, t; }"
        : "=r"(a) : "l"(p));
    return a;
}
__device__ __forceinline__ void mma_tf32(float* c, const uint32_t* a,
                                         uint32_t b0, uint32_t b1) {
    asm volatile(
        "mma.sync.aligned.m16n8k8.row.col.f32.tf32.tf32.f32 "
        "{%0,%1,%2,%3}, {%4,%5,%6,%7}, {%8,%9}, {%0,%1,%2,%3};"
        : "+f"(c[0]), "+f"(c[1]), "+f"(c[2]), "+f"(c[3])
        : "r"(a[0]), "r"(a[1]), "r"(a[2]), "r"(a[3]), "r"(b0), "r"(b1));
}
#define CP_ASYNC4(dst, src) \
    asm volatile("cp.async.ca.shared.global [%0], [%1], 4;" :: "r"(dst), "l"(src))
#define CP_COMMIT() asm volatile("cp.async.commit_group;" ::: "memory")
#define CP_WAIT(n)  asm volatile("cp.async.wait_group %0;" :: "n"(n) : "memory")

__global__ void round_tf32_kernel(const float4* __restrict__ in,
                                  float4* __restrict__ out, int n4) {
    int i = blockIdx.x * blockDim.x + threadIdx.x;
    if (i >= n4) return;
    float4 v = in[i];
    v.x = rna_tf32(v.x); v.y = rna_tf32(v.y);
    v.z = rna_tf32(v.z); v.w = rna_tf32(v.w);
    out[i] = v;
}

// ---------------------------------------------------------------------------
// tf32 mma.sync GEMM: C[M,Nc] = A[M,K] @ B[Nc,K]^T (unchanged from R3)
// ---------------------------------------------------------------------------
template <int SCATTER_C>
__global__ __launch_bounds__(256, 2)
void tf32_gemm(const float* __restrict__ Ag, const float* __restrict__ Bg,
               float* __restrict__ Cg) {
    __shared__ __align__(16) float As[4096];
    __shared__ __align__(16) float Bs[4096];

    const int tid  = threadIdx.x;
    const int lane = tid & 31;
    const int wid  = tid >> 5;
    const int wm   = wid & 3;
    const int wn   = wid >> 2;
    const int m0   = blockIdx.y * 128;
    const int n0   = blockIdx.x * 128;

    float c[2][8][4];
#pragma unroll
    for (int mi = 0; mi < 2; mi++)
#pragma unroll
        for (int ni = 0; ni < 8; ni++)
#pragma unroll
            for (int j = 0; j < 4; j++) c[mi][ni][j] = 0.f;

    float4 pa[4], pb[4];

    auto load_tile = [&](int kt) {
#pragma unroll
        for (int i = 0; i < 4; i++) {
            int idx = tid + i * 256;
            int row = idx >> 3, c4 = idx & 7;
            pa[i] = *(const float4*)(Ag + (size_t)(m0 + row) * Kdim + kt * 32 + c4 * 4);
            pb[i] = *(const float4*)(Bg + (size_t)(n0 + row) * Kdim + kt * 32 + c4 * 4);
        }
    };

    load_tile(0);

    constexpr int NKT = Kdim / 32;
    for (int kt = 0; kt < NKT; kt++) {
#pragma unroll
        for (int i = 0; i < 4; i++) {
            int idx = tid + i * 256;
            int row = idx >> 3, c4 = idx & 7;
            {
                int mt = row >> 4, r = row & 15, ks = c4 >> 1, hi = c4 & 1;
                int reg = ((r >> 3) & 1) | (hi << 1);
                float* ba = &As[(mt * 4 + ks) * 128 + (r & 7) * 16 + reg];
                ba[0] = pa[i].x; ba[4] = pa[i].y; ba[8] = pa[i].z; ba[12] = pa[i].w;
            }
            {
                int nt = row >> 3, g = row & 7, ks = c4 >> 1, reg = c4 & 1;
                float* bb = &Bs[(nt * 4 + ks) * 64 + g * 8 + reg];
                bb[0] = pb[i].x; bb[2] = pb[i].y; bb[4] = pb[i].z; bb[6] = pb[i].w;
            }
        }
        __syncthreads();

        if (kt + 1 < NKT) load_tile(kt + 1);

#pragma unroll
        for (int ks = 0; ks < 4; ks++) {
            uint32_t af[2][4];
#pragma unroll
            for (int mi = 0; mi < 2; mi++) {
                float4 t = *(const float4*)&As[((wm * 2 + mi) * 4 + ks) * 128 + lane * 4];
                af[mi][0] = __float_as_uint(t.x);
                af[mi][1] = __float_as_uint(t.y);
                af[mi][2] = __float_as_uint(t.z);
                af[mi][3] = __float_as_uint(t.w);
            }
#pragma unroll
            for (int ni = 0; ni < 8; ni++) {
                float2 tb = *(const float2*)&Bs[((wn * 8 + ni) * 4 + ks) * 64 + lane * 2];
                uint32_t b0 = __float_as_uint(tb.x), b1 = __float_as_uint(tb.y);
#pragma unroll
                for (int mi = 0; mi < 2; mi++)
                    mma_tf32(c[mi][ni], af[mi], b0, b1);
            }
        }
        __syncthreads();
    }

    const int gid = lane >> 2, tig = lane & 3;
#pragma unroll
    for (int mi = 0; mi < 2; mi++) {
#pragma unroll
        for (int ni = 0; ni < 8; ni++) {
            int n = n0 + wn * 64 + ni * 8 + tig * 2;
#pragma unroll
            for (int half = 0; half < 2; half++) {
                int m = m0 + wm * 32 + mi * 16 + gid + half * 8;
                float2 v = make_float2(c[mi][ni][half * 2], c[mi][ni][half * 2 + 1]);
                size_t dst;
                if (SCATTER_C) {
                    int b2 = m >> 11, np = m & 2047, h2 = n >> 7, a0 = n & 127;
                    dst = ((((size_t)b2 * H + h2) * N) + np) * A + a0;
                } else {
                    dst = (size_t)m * 2048 + n;
                }
                *(float2*)(Cg + dst) = v;
            }
        }
    }
}

// ---------------------------------------------------------------------------
// RoPE (interleaved pairs), in place on Q and K (head-major layout).
// ---------------------------------------------------------------------------
__global__ void rope_kernel(float* __restrict__ Q, float* __restrict__ K) {
    int idx = blockIdx.x * blockDim.x + threadIdx.x;
    int i = idx & 63;
    int npos = (idx >> 6) & 2047;
    float freq = __powf(10000.0f, -(float)i * (1.0f / 63.0f));
    float th = (float)npos * freq;
    float s, c;
    sincosf(th, &s, &c);
    size_t base = (size_t)idx * 2;

    float q0 = Q[base], q1 = Q[base + 1];
    Q[base]     = q0 * c - q1 * s;
    Q[base + 1] = q1 * c + q0 * s;

    float k0 = K[base], k1 = K[base + 1];
    K[base]     = k0 * c - k1 * s;
    K[base + 1] = k1 * c + k0 * s;
}

// ---------------------------------------------------------------------------
// Tensor-core causal flash attention (tf32 mma.sync).
// CTA: 128 queries, 256 threads (8 warps), warp owns 16 query rows.
// K tile: 64 keys. K/V double-buffered via 4B cp.async in B-frag order.
// Output -> [b*n, h*a], rna-rounded for Wo GEMM.
// ---------------------------------------------------------------------------
constexpr int AQT = 128;
constexpr int AKT = 64;
constexpr int QS_FLOATS = AQT * 128;      // 16384
constexpr int KT_FLOATS = AKT * 128;      // 8192
constexpr int ATTN_SMEM = (QS_FLOATS + 4 * KT_FLOATS) * 4;  // 196608 B

__global__ __launch_bounds__(256, 1)
void attn_mma_kernel(const float* __restrict__ Q, const float* __restrict__ K,
                     const float* __restrict__ V, float* __restrict__ O) {
    extern __shared__ float smx[];
    float* Qs = smx;
    float* Ks = smx + QS_FLOATS;                   // 2 bufs x 8192
    float* Vs = smx + QS_FLOATS + 2 * KT_FLOATS;   // 2 bufs x 8192

    const int tid  = threadIdx.x;
    const int lane = tid & 31;
    const int wid  = tid >> 5;
    const int gid  = lane >> 2, tig = lane & 3;
    const int bh   = blockIdx.y;
    const int qt   = gridDim.x - 1 - blockIdx.x;   // heavy tiles first
    const int q0   = qt * AQT;

    const float* Qb = Q + (size_t)bh * N * A;
    const float* Kb = K + (size_t)bh * N * A;
    const float* Vb = V + (size_t)bh * N * A;

    // ---- stage Q (scale + rna) into A-frag order ----
    const float scl = 0.08838834764831845f;   // 1/sqrt(128)
#pragma unroll
    for (int i = 0; i < 16; i++) {
        int idx = tid + i * 256;
        int row = idx >> 5, c4 = idx & 31;
        float4 v = *(const float4*)(Qb + (size_t)(q0 + row) * A + c4 * 4);
        int w = row >> 4, r = row & 15, kf = c4 >> 1;
        int rg = ((r >> 3) & 1) | ((c4 & 1) << 1);
        float* dst = Qs + (w * 16 + kf) * 128 + ((r & 7) * 4) * 4 + rg;
        dst[0]  = rna_tf32(v.x * scl);
        dst[4]  = rna_tf32(v.y * scl);
        dst[8]  = rna_tf32(v.z * scl);
        dst[12] = rna_tf32(v.w * scl);
    }
    __syncthreads();

    uint32_t qf[16][4];
#pragma unroll
    for (int kd = 0; kd < 16; kd++) {
        float4 t = *(const float4*)(Qs + (wid * 16 + kd) * 128 + lane * 4);
        qf[kd][0] = __float_as_uint(t.x);
        qf[kd][1] = __float_as_uint(t.y);
        qf[kd][2] = __float_as_uint(t.z);
        qf[kd][3] = __float_as_uint(t.w);
    }

    // ---- staging constants ----
    const uint32_t ks_base = smem_u32(Ks);
    const uint32_t vs_base = smem_u32(Vs);
    const int sd   = tid & 127;         // d-index this thread stages
    const int key0 = tid >> 7;          // 0/1
    const int s_kd  = sd >> 3;          // d>>3 (kfrag for K, nfrag for V)
    const int s_d3  = sd & 3;
    const int s_rgk = (sd >> 2) & 1;
    const int s_ln7 = (sd & 7) * 4;

    auto stage = [&](int kt, int buf) {
        const float* Kg = Kb + (size_t)(kt * AKT) * A + sd;
        const float* Vg = Vb + (size_t)(kt * AKT) * A + sd;
        uint32_t kb = ks_base + buf * (KT_FLOATS * 4);
        uint32_t vb = vs_base + buf * (KT_FLOATS * 4);
#pragma unroll
        for (int i = 0; i < 32; i++) {
            int key = key0 + 2 * i;
            // K frag: kfrag=d>>3, nfrag=key>>3, lane=(key&7)*4+(d&3), reg=(d>>2)&1
            int nk  = key >> 3;
            int lnk = (key & 7) * 4 + s_d3;
            uint32_t ka = kb + (((s_kd * 8 + nk) * 32 + lnk) * 2 + s_rgk) * 4;
            CP_ASYNC4(ka, Kg + key * 128);
            // V frag: kfrag=key>>3, nfrag=d>>3, lane=(d&7)*4+(key&3), reg=(key>>2)&1
            int kfv = key >> 3;
            int lnv = s_ln7 + (key & 3);
            int rgv = (key >> 2) & 1;
            uint32_t va = vb + (((kfv * 16 + s_kd) * 32 + lnv) * 2 + rgv) * 4;
            CP_ASYNC4(va, Vg + key * 128);
        }
    };

    const int nkt  = 2 * qt + 2;                 // CTA-wide k-tiles
    const int nktw = 2 * qt + 1 + (wid >> 2);    // this warp's k-tiles

    float o[16][4];
#pragma unroll
    for (int nf = 0; nf < 16; nf++)
#pragma unroll
        for (int j = 0; j < 4; j++) o[nf][j] = 0.f;
    float m0 = -1e30f, m1 = -1e30f, l0 = 0.f, l1 = 0.f;

    const int row0 = q0 + wid * 16 + gid;
    const int row1 = row0 + 8;

    stage(0, 0); CP_COMMIT();
    stage(1, 1); CP_COMMIT();

    for (int kt = 0; kt < nkt; kt++) {
        const int buf = kt & 1;
        if (kt < nkt - 1) { CP_WAIT(1); } else { CP_WAIT(0); }
        __syncthreads();

        if (kt < nktw) {
            const float* kbuf = Ks + buf * KT_FLOATS;
            const float* vbuf = Vs + buf * KT_FLOATS;

            // ---- S = Q K^T ----
            float s[8][4];
#pragma unroll
            for (int nk = 0; nk < 8; nk++)
#pragma unroll
                for (int j = 0; j < 4; j++) s[nk][j] = 0.f;

#pragma unroll
            for (int kd = 0; kd < 16; kd++) {
#pragma unroll
                for (int nk = 0; nk < 8; nk++) {
                    float2 bb = *(const float2*)(kbuf + ((kd * 8 + nk) * 32 + lane) * 2);
                    mma_tf32(s[nk], qf[kd],
                             __float_as_uint(bb.x), __float_as_uint(bb.y));
                }
            }

            // ---- causal mask (diagonal tile only) ----
            if (kt == nktw - 1) {
                int colb = kt * AKT + 2 * tig;
#pragma unroll
                for (int nk = 0; nk < 8; nk++) {
                    int c0 = colb + nk * 8;
                    if (c0     > row0) s[nk][0] = -1e30f;
                    if (c0 + 1 > row0) s[nk][1] = -1e30f;
                    if (c0     > row1) s[nk][2] = -1e30f;
                    if (c0 + 1 > row1) s[nk][3] = -1e30f;
                }
            }

            // ---- online softmax ----
            float mx0 = -1e30f, mx1 = -1e30f;
#pragma unroll
            for (int nk = 0; nk < 8; nk++) {
                mx0 = fmaxf(mx0, fmaxf(s[nk][0], s[nk][1]));
                mx1 = fmaxf(mx1, fmaxf(s[nk][2], s[nk][3]));
            }
            mx0 = fmaxf(mx0, __shfl_xor_sync(0xffffffffu, mx0, 1));
            mx0 = fmaxf(mx0, __shfl_xor_sync(0xffffffffu, mx0, 2));
            mx1 = fmaxf(mx1, __shfl_xor_sync(0xffffffffu, mx1, 1));
            mx1 = fmaxf(mx1, __shfl_xor_sync(0xffffffffu, mx1, 2));
            float mn0 = fmaxf(m0, mx0), mn1 = fmaxf(m1, mx1);
            float cor0 = __expf(m0 - mn0), cor1 = __expf(m1 - mn1);
            m0 = mn0; m1 = mn1;

            float rs0 = 0.f, rs1 = 0.f;
#pragma unroll
            for (int nk = 0; nk < 8; nk++) {
                s[nk][0] = __expf(s[nk][0] - mn0);
                s[nk][1] = __expf(s[nk][1] - mn0);
                s[nk][2] = __expf(s[nk][2] - mn1);
                s[nk][3] = __expf(s[nk][3] - mn1);
                rs0 += s[nk][0] + s[nk][1];
                rs1 += s[nk][2] + s[nk][3];
            }
            rs0 += __shfl_xor_sync(0xffffffffu, rs0, 1);
            rs0 += __shfl_xor_sync(0xffffffffu, rs0, 2);
            rs1 += __shfl_xor_sync(0xffffffffu, rs1, 1);
            rs1 += __shfl_xor_sync(0xffffffffu, rs1, 2);
            l0 = l0 * cor0 + rs0;
            l1 = l1 * cor1 + rs1;

#pragma unroll
            for (int nf = 0; nf < 16; nf++) {
                o[nf][0] *= cor0; o[nf][1] *= cor0;
                o[nf][2] *= cor1; o[nf][3] *= cor1;
            }

            // ---- O += P V : convert P C-layout -> A-frag via quad shuffles ----
            const int lA = (gid << 2) + (tig >> 1);
            const int lB = lA + 2;
            const bool odd = tig & 1;
#pragma unroll
            for (int kf = 0; kf < 8; kf++) {
                float p0 = s[kf][0], p1 = s[kf][1], p2 = s[kf][2], p3 = s[kf][3];
                float x0 = __shfl_sync(0xffffffffu, p0, lA);
                float x1 = __shfl_sync(0xffffffffu, p1, lA);
                float y0 = __shfl_sync(0xffffffffu, p0, lB);
                float y1 = __shfl_sync(0xffffffffu, p1, lB);
                float z0 = __shfl_sync(0xffffffffu, p2, lA);
                float z1 = __shfl_sync(0xffffffffu, p3, lA);
                float w0 = __shfl_sync(0xffffffffu, p2, lB);
                float w1 = __shfl_sync(0xffffffffu, p3, lB);
                uint32_t a[4];
                a[0] = rna_tf32_bits(odd ? x1 : x0);   // (gid,   tig)
                a[1] = rna_tf32_bits(odd ? z1 : z0);   // (gid+8, tig)
                a[2] = rna_tf32_bits(odd ? y1 : y0);   // (gid,   tig+4)
                a[3] = rna_tf32_bits(odd ? w1 : w0);   // (gid+8, tig+4)
#pragma unroll
                for (int nf = 0; nf < 16; nf++) {
                    float2 bb = *(const float2*)(vbuf + ((kf * 16 + nf) * 32 + lane) * 2);
                    mma_tf32(o[nf], a,
                             __float_as_uint(bb.x), __float_as_uint(bb.y));
                }
            }
        }

        __syncthreads();
        if (kt + 2 < nkt) { stage(kt + 2, buf); CP_COMMIT(); }
    }

    // ---- write output: [b*n, h*a], rna for Wo GEMM ----
    const float il0 = 1.f / l0, il1 = 1.f / l1;
    const int b2 = bh >> 4, h2 = bh & 15;
    float* o0 = O + (size_t)(b2 * N + row0) * HD + h2 * A;
    float* o1 = O + (size_t)(b2 * N + row1) * HD + h2 * A;
#pragma unroll
    for (int nf = 0; nf < 16; nf++) {
        int col = nf * 8 + 2 * tig;
        *(float2*)(o0 + col) = make_float2(rna_tf32(o[nf][0] * il0),
                                           rna_tf32(o[nf][1] * il0));
        *(float2*)(o1 + col) = make_float2(rna_tf32(o[nf][2] * il1),
                                           rna_tf32(o[nf][3] * il1));
    }
}

// ---------------------------------------------------------------------------
extern "C" void kernel_launch(void* const* d_in, const int* in_sizes, int n_in,
                              void* d_out, int out_size) {
    const float* q  = (const float*)d_in[0];
    const float* Wq = (const float*)d_in[1];
    const float* Wk = (const float*)d_in[2];
    const float* Wv = (const float*)d_in[3];
    const float* Wo = (const float*)d_in[4];
    float* out = (float*)d_out;

    float *qr, *Wqr, *Wkr, *Wvr, *Wor, *Qp, *Kp, *Vp, *AOp;
    cudaGetSymbolAddress((void**)&qr,  g_qr);
    cudaGetSymbolAddress((void**)&Wqr, g_Wqr);
    cudaGetSymbolAddress((void**)&Wkr, g_Wkr);
    cudaGetSymbolAddress((void**)&Wvr, g_Wvr);
    cudaGetSymbolAddress((void**)&Wor, g_Wor);
    cudaGetSymbolAddress((void**)&Qp,  g_Q);
    cudaGetSymbolAddress((void**)&Kp,  g_K);
    cudaGetSymbolAddress((void**)&Vp,  g_V);
    cudaGetSymbolAddress((void**)&AOp, g_AO);

    // tf32 pre-rounding (round-to-nearest -> unbiased tensor MMA)
    {
        int n4q = Mdim * Kdim / 4;
        int n4w = HD * W / 4;
        round_tf32_kernel<<<n4q / 256, 256>>>((const float4*)q,  (float4*)qr,  n4q);
        round_tf32_kernel<<<n4w / 256, 256>>>((const float4*)Wq, (float4*)Wqr, n4w);
        round_tf32_kernel<<<n4w / 256, 256>>>((const float4*)Wk, (float4*)Wkr, n4w);
        round_tf32_kernel<<<n4w / 256, 256>>>((const float4*)Wv, (float4*)Wvr, n4w);
        round_tf32_kernel<<<n4w / 256, 256>>>((const float4*)Wo, (float4*)Wor, n4w);
    }

    cudaFuncSetAttribute(attn_mma_kernel,
                         cudaFuncAttributeMaxDynamicSharedMemorySize, ATTN_SMEM);

    dim3 gg(2048 / 128, Mdim / 128);   // (16, 32)

    // QKV projections -> head-major scratch (tensor-core tf32)
    tf32_gemm<1><<<gg, 256>>>(qr, Wqr, Qp);
    tf32_gemm<1><<<gg, 256>>>(qr, Wkr, Kp);
    tf32_gemm<1><<<gg, 256>>>(qr, Wvr, Vp);

    // RoPE on Q and K
    int npairs = B * H * N * (A / 2);
    rope_kernel<<<npairs / 256, 256>>>(Qp, Kp);

    // tensor-core causal flash attention
    attn_mma_kernel<<<dim3(N / AQT, B * H), 256, ATTN_SMEM>>>(Qp, Kp, Vp, AOp);

    // output projection
    tf32_gemm<0><<<gg, 256>>>(AOp, Wor, out);
}

// round 5
// speedup vs baseline: 5.1395x; 1.0510x over previous
#include <cuda_runtime.h>
#include <cstdint>
#include <math.h>

// Problem constants
constexpr int B = 2;
constexpr int H = 16;
constexpr int N = 2048;
constexpr int A = 128;           // head dim
constexpr int W = 2048;          // model width
constexpr int HD = H * A;        // 2048
constexpr int Mdim = B * N;      // 4096
constexpr int Kdim = W;          // 2048

// Scratch (device globals — no allocation allowed)
__device__ float g_Q  [B * H * N * A];   // head-major
__device__ float g_K  [B * H * N * A];
__device__ float g_V  [B * H * N * A];
__device__ float g_AO [Mdim * HD];       // [b*n, h*a], tf32-rounded

// ---------------------------------------------------------------------------
// helpers
// ---------------------------------------------------------------------------
__device__ __forceinline__ float rna_tf32(float x) {
    uint32_t u;
    asm("cvt.rna.tf32.f32 %0, %1;" : "=r"(u) : "f"(x));
    return __uint_as_float(u);
}
__device__ __forceinline__ uint32_t rna_tf32_bits(float x) {
    uint32_t u;
    asm("cvt.rna.tf32.f32 %0, %1;" : "=r"(u) : "f"(x));
    return u;
}
__device__ __forceinline__ uint32_t smem_u32(const void* p) {
    uint32_t a;
    asm("{ .reg .u64 t; cvta.to.shared.u64 t, %1; cvt.u32.u64 %0, t; }"
        : "=r"(a) : "l"(p));
    return a;
}
__device__ __forceinline__ void mma_tf32(float* c, const uint32_t* a,
                                         uint32_t b0, uint32_t b1) {
    asm volatile(
        "mma.sync.aligned.m16n8k8.row.col.f32.tf32.tf32.f32 "
        "{%0,%1,%2,%3}, {%4,%5,%6,%7}, {%8,%9}, {%0,%1,%2,%3};"
        : "+f"(c[0]), "+f"(c[1]), "+f"(c[2]), "+f"(c[3])
        : "r"(a[0]), "r"(a[1]), "r"(a[2]), "r"(a[3]), "r"(b0), "r"(b1));
}
#define CP_ASYNC4(dst, src) \
    asm volatile("cp.async.ca.shared.global [%0], [%1], 4;" :: "r"(dst), "l"(src))
#define CP_COMMIT() asm volatile("cp.async.commit_group;" ::: "memory")
#define CP_WAIT(n)  asm volatile("cp.async.wait_group %0;" :: "n"(n) : "memory")

// ---------------------------------------------------------------------------
// tf32 mma.sync GEMM body: C[M,Nc] = A[M,K] @ B[Nc,K]^T.
// 128x128 CTA tile, BK=32, 8 warps (4m x 2n), warp tile 32x64.
// Double-buffered fragment-order smem; ONE syncthreads per k-tile:
//   [STS(kt) -> sync -> LDG(kt+1) -> compute(kt)]
// rna_tf32 applied inline during staging (inputs are raw fp32).
// ---------------------------------------------------------------------------
constexpr int GEMM_SMEM = 2 * (4096 + 4096) * 4;   // 65536 B

template <int SCATTER_C>
__device__ __forceinline__ void gemm_body(const float* __restrict__ Ag,
                                          const float* __restrict__ Bg,
                                          float* __restrict__ Cg) {
    extern __shared__ float gs[];
    float* As = gs;            // [2][4096]
    float* Bs = gs + 2 * 4096; // [2][4096]

    const int tid  = threadIdx.x;
    const int lane = tid & 31;
    const int wid  = tid >> 5;
    const int wm   = wid & 3;
    const int wn   = wid >> 2;
    const int m0   = blockIdx.y * 128;
    const int n0   = blockIdx.x * 128;

    float c[2][8][4];
#pragma unroll
    for (int mi = 0; mi < 2; mi++)
#pragma unroll
        for (int ni = 0; ni < 8; ni++)
#pragma unroll
            for (int j = 0; j < 4; j++) c[mi][ni][j] = 0.f;

    float4 pa[4], pb[4];

    auto load_tile = [&](int kt) {
#pragma unroll
        for (int i = 0; i < 4; i++) {
            int idx = tid + i * 256;
            int row = idx >> 3, c4 = idx & 7;
            pa[i] = *(const float4*)(Ag + (size_t)(m0 + row) * Kdim + kt * 32 + c4 * 4);
            pb[i] = *(const float4*)(Bg + (size_t)(n0 + row) * Kdim + kt * 32 + c4 * 4);
        }
    };

    auto store_tile = [&](int buf) {
        float* Ab = As + buf * 4096;
        float* Bb = Bs + buf * 4096;
#pragma unroll
        for (int i = 0; i < 4; i++) {
            int idx = tid + i * 256;
            int row = idx >> 3, c4 = idx & 7;
            {   // A frag order
                int mt = row >> 4, r = row & 15, ks = c4 >> 1, hi = c4 & 1;
                int reg = ((r >> 3) & 1) | (hi << 1);
                float* ba = &Ab[(mt * 4 + ks) * 128 + (r & 7) * 16 + reg];
                ba[0]  = rna_tf32(pa[i].x); ba[4]  = rna_tf32(pa[i].y);
                ba[8]  = rna_tf32(pa[i].z); ba[12] = rna_tf32(pa[i].w);
            }
            {   // B frag order
                int nt = row >> 3, g = row & 7, ks = c4 >> 1, reg = c4 & 1;
                float* bb = &Bb[(nt * 4 + ks) * 64 + g * 8 + reg];
                bb[0] = rna_tf32(pb[i].x); bb[2] = rna_tf32(pb[i].y);
                bb[4] = rna_tf32(pb[i].z); bb[6] = rna_tf32(pb[i].w);
            }
        }
    };

    load_tile(0);

    constexpr int NKT = Kdim / 32;   // 64
    for (int kt = 0; kt < NKT; kt++) {
        const int buf = kt & 1;
        store_tile(buf);
        __syncthreads();
        if (kt + 1 < NKT) load_tile(kt + 1);

        const float* Ab = As + buf * 4096;
        const float* Bb = Bs + buf * 4096;
#pragma unroll
        for (int ks = 0; ks < 4; ks++) {
            uint32_t af[2][4];
#pragma unroll
            for (int mi = 0; mi < 2; mi++) {
                float4 t = *(const float4*)&Ab[((wm * 2 + mi) * 4 + ks) * 128 + lane * 4];
                af[mi][0] = __float_as_uint(t.x);
                af[mi][1] = __float_as_uint(t.y);
                af[mi][2] = __float_as_uint(t.z);
                af[mi][3] = __float_as_uint(t.w);
            }
#pragma unroll
            for (int ni = 0; ni < 8; ni++) {
                float2 tb = *(const float2*)&Bb[((wn * 8 + ni) * 4 + ks) * 64 + lane * 2];
                uint32_t b0 = __float_as_uint(tb.x), b1 = __float_as_uint(tb.y);
#pragma unroll
                for (int mi = 0; mi < 2; mi++)
                    mma_tf32(c[mi][ni], af[mi], b0, b1);
            }
        }
        // no trailing sync: next store targets the other buffer; safety via
        // sync(kt) ordering (all warps past store(kt) => done compute(kt-1)).
        __syncthreads();
    }

    const int gid = lane >> 2, tig = lane & 3;
#pragma unroll
    for (int mi = 0; mi < 2; mi++) {
#pragma unroll
        for (int ni = 0; ni < 8; ni++) {
            int n = n0 + wn * 64 + ni * 8 + tig * 2;
#pragma unroll
            for (int half = 0; half < 2; half++) {
                int m = m0 + wm * 32 + mi * 16 + gid + half * 8;
                float2 v = make_float2(c[mi][ni][half * 2], c[mi][ni][half * 2 + 1]);
                size_t dst;
                if (SCATTER_C) {
                    int b2 = m >> 11, np = m & 2047, h2 = n >> 7, a0 = n & 127;
                    dst = ((((size_t)b2 * H + h2) * N) + np) * A + a0;
                } else {
                    dst = (size_t)m * 2048 + n;
                }
                *(float2*)(Cg + dst) = v;
            }
        }
    }
}

// Fused QKV: gridDim.z selects weight/output. Same A operand across z ->
// concurrent CTAs at same (x,y) hit L2 on A tiles.
__global__ __launch_bounds__(256, 2)
void qkv_gemm(const float* __restrict__ q,
              const float* __restrict__ Wq, const float* __restrict__ Wk,
              const float* __restrict__ Wv,
              float* __restrict__ Qp, float* __restrict__ Kp,
              float* __restrict__ Vp) {
    const int z = blockIdx.z;
    const float* Bg = (z == 0) ? Wq : (z == 1) ? Wk : Wv;
    float*       Cg = (z == 0) ? Qp : (z == 1) ? Kp : Vp;
    gemm_body<1>(q, Bg, Cg);
}

__global__ __launch_bounds__(256, 2)
void out_gemm(const float* __restrict__ Ag, const float* __restrict__ Bg,
              float* __restrict__ Cg) {
    gemm_body<0>(Ag, Bg, Cg);
}

// ---------------------------------------------------------------------------
// RoPE (interleaved pairs), in place on Q and K (head-major layout).
// ---------------------------------------------------------------------------
__global__ void rope_kernel(float* __restrict__ Q, float* __restrict__ K) {
    int idx = blockIdx.x * blockDim.x + threadIdx.x;
    int i = idx & 63;
    int npos = (idx >> 6) & 2047;
    float freq = __powf(10000.0f, -(float)i * (1.0f / 63.0f));
    float th = (float)npos * freq;
    float s, c;
    sincosf(th, &s, &c);
    size_t base = (size_t)idx * 2;

    float q0 = Q[base], q1 = Q[base + 1];
    Q[base]     = q0 * c - q1 * s;
    Q[base + 1] = q1 * c + q0 * s;

    float k0 = K[base], k1 = K[base + 1];
    K[base]     = k0 * c - k1 * s;
    K[base + 1] = k1 * c + k0 * s;
}

// ---------------------------------------------------------------------------
// Tensor-core causal flash attention (tf32 mma.sync). Unchanged from R4.
// ---------------------------------------------------------------------------
constexpr int AQT = 128;
constexpr int AKT = 64;
constexpr int QS_FLOATS = AQT * 128;
constexpr int KT_FLOATS = AKT * 128;
constexpr int ATTN_SMEM = (QS_FLOATS + 4 * KT_FLOATS) * 4;  // 196608 B

__global__ __launch_bounds__(256, 1)
void attn_mma_kernel(const float* __restrict__ Q, const float* __restrict__ K,
                     const float* __restrict__ V, float* __restrict__ O) {
    extern __shared__ float smx[];
    float* Qs = smx;
    float* Ks = smx + QS_FLOATS;
    float* Vs = smx + QS_FLOATS + 2 * KT_FLOATS;

    const int tid  = threadIdx.x;
    const int lane = tid & 31;
    const int wid  = tid >> 5;
    const int gid  = lane >> 2, tig = lane & 3;
    const int bh   = blockIdx.y;
    const int qt   = gridDim.x - 1 - blockIdx.x;
    const int q0   = qt * AQT;

    const float* Qb = Q + (size_t)bh * N * A;
    const float* Kb = K + (size_t)bh * N * A;
    const float* Vb = V + (size_t)bh * N * A;

    const float scl = 0.08838834764831845f;   // 1/sqrt(128)
#pragma unroll
    for (int i = 0; i < 16; i++) {
        int idx = tid + i * 256;
        int row = idx >> 5, c4 = idx & 31;
        float4 v = *(const float4*)(Qb + (size_t)(q0 + row) * A + c4 * 4);
        int w = row >> 4, r = row & 15, kf = c4 >> 1;
        int rg = ((r >> 3) & 1) | ((c4 & 1) << 1);
        float* dst = Qs + (w * 16 + kf) * 128 + ((r & 7) * 4) * 4 + rg;
        dst[0]  = rna_tf32(v.x * scl);
        dst[4]  = rna_tf32(v.y * scl);
        dst[8]  = rna_tf32(v.z * scl);
        dst[12] = rna_tf32(v.w * scl);
    }
    __syncthreads();

    uint32_t qf[16][4];
#pragma unroll
    for (int kd = 0; kd < 16; kd++) {
        float4 t = *(const float4*)(Qs + (wid * 16 + kd) * 128 + lane * 4);
        qf[kd][0] = __float_as_uint(t.x);
        qf[kd][1] = __float_as_uint(t.y);
        qf[kd][2] = __float_as_uint(t.z);
        qf[kd][3] = __float_as_uint(t.w);
    }

    const uint32_t ks_base = smem_u32(Ks);
    const uint32_t vs_base = smem_u32(Vs);
    const int sd   = tid & 127;
    const int key0 = tid >> 7;
    const int s_kd  = sd >> 3;
    const int s_d3  = sd & 3;
    const int s_rgk = (sd >> 2) & 1;
    const int s_ln7 = (sd & 7) * 4;

    auto stage = [&](int kt, int buf) {
        const float* Kg = Kb + (size_t)(kt * AKT) * A + sd;
        const float* Vg = Vb + (size_t)(kt * AKT) * A + sd;
        uint32_t kb = ks_base + buf * (KT_FLOATS * 4);
        uint32_t vb = vs_base + buf * (KT_FLOATS * 4);
#pragma unroll
        for (int i = 0; i < 32; i++) {
            int key = key0 + 2 * i;
            int nk  = key >> 3;
            int lnk = (key & 7) * 4 + s_d3;
            uint32_t ka = kb + (((s_kd * 8 + nk) * 32 + lnk) * 2 + s_rgk) * 4;
            CP_ASYNC4(ka, Kg + key * 128);
            int kfv = key >> 3;
            int lnv = s_ln7 + (key & 3);
            int rgv = (key >> 2) & 1;
            uint32_t va = vb + (((kfv * 16 + s_kd) * 32 + lnv) * 2 + rgv) * 4;
            CP_ASYNC4(va, Vg + key * 128);
        }
    };

    const int nkt  = 2 * qt + 2;
    const int nktw = 2 * qt + 1 + (wid >> 2);

    float o[16][4];
#pragma unroll
    for (int nf = 0; nf < 16; nf++)
#pragma unroll
        for (int j = 0; j < 4; j++) o[nf][j] = 0.f;
    float m0 = -1e30f, m1 = -1e30f, l0 = 0.f, l1 = 0.f;

    const int row0 = q0 + wid * 16 + gid;
    const int row1 = row0 + 8;

    stage(0, 0); CP_COMMIT();
    stage(1, 1); CP_COMMIT();

    for (int kt = 0; kt < nkt; kt++) {
        const int buf = kt & 1;
        if (kt < nkt - 1) { CP_WAIT(1); } else { CP_WAIT(0); }
        __syncthreads();

        if (kt < nktw) {
            const float* kbuf = Ks + buf * KT_FLOATS;
            const float* vbuf = Vs + buf * KT_FLOATS;

            float s[8][4];
#pragma unroll
            for (int nk = 0; nk < 8; nk++)
#pragma unroll
                for (int j = 0; j < 4; j++) s[nk][j] = 0.f;

#pragma unroll
            for (int kd = 0; kd < 16; kd++) {
#pragma unroll
                for (int nk = 0; nk < 8; nk++) {
                    float2 bb = *(const float2*)(kbuf + ((kd * 8 + nk) * 32 + lane) * 2);
                    mma_tf32(s[nk], qf[kd],
                             __float_as_uint(bb.x), __float_as_uint(bb.y));
                }
            }

            if (kt == nktw - 1) {
                int colb = kt * AKT + 2 * tig;
#pragma unroll
                for (int nk = 0; nk < 8; nk++) {
                    int c0 = colb + nk * 8;
                    if (c0     > row0) s[nk][0] = -1e30f;
                    if (c0 + 1 > row0) s[nk][1] = -1e30f;
                    if (c0     > row1) s[nk][2] = -1e30f;
                    if (c0 + 1 > row1) s[nk][3] = -1e30f;
                }
            }

            float mx0 = -1e30f, mx1 = -1e30f;
#pragma unroll
            for (int nk = 0; nk < 8; nk++) {
                mx0 = fmaxf(mx0, fmaxf(s[nk][0], s[nk][1]));
                mx1 = fmaxf(mx1, fmaxf(s[nk][2], s[nk][3]));
            }
            mx0 = fmaxf(mx0, __shfl_xor_sync(0xffffffffu, mx0, 1));
            mx0 = fmaxf(mx0, __shfl_xor_sync(0xffffffffu, mx0, 2));
            mx1 = fmaxf(mx1, __shfl_xor_sync(0xffffffffu, mx1, 1));
            mx1 = fmaxf(mx1, __shfl_xor_sync(0xffffffffu, mx1, 2));
            float mn0 = fmaxf(m0, mx0), mn1 = fmaxf(m1, mx1);
            float cor0 = __expf(m0 - mn0), cor1 = __expf(m1 - mn1);
            m0 = mn0; m1 = mn1;

            float rs0 = 0.f, rs1 = 0.f;
#pragma unroll
            for (int nk = 0; nk < 8; nk++) {
                s[nk][0] = __expf(s[nk][0] - mn0);
                s[nk][1] = __expf(s[nk][1] - mn0);
                s[nk][2] = __expf(s[nk][2] - mn1);
                s[nk][3] = __expf(s[nk][3] - mn1);
                rs0 += s[nk][0] + s[nk][1];
                rs1 += s[nk][2] + s[nk][3];
            }
            rs0 += __shfl_xor_sync(0xffffffffu, rs0, 1);
            rs0 += __shfl_xor_sync(0xffffffffu, rs0, 2);
            rs1 += __shfl_xor_sync(0xffffffffu, rs1, 1);
            rs1 += __shfl_xor_sync(0xffffffffu, rs1, 2);
            l0 = l0 * cor0 + rs0;
            l1 = l1 * cor1 + rs1;

#pragma unroll
            for (int nf = 0; nf < 16; nf++) {
                o[nf][0] *= cor0; o[nf][1] *= cor0;
                o[nf][2] *= cor1; o[nf][3] *= cor1;
            }

            const int lA = (gid << 2) + (tig >> 1);
            const int lB = lA + 2;
            const bool odd = tig & 1;
#pragma unroll
            for (int kf = 0; kf < 8; kf++) {
                float p0 = s[kf][0], p1 = s[kf][1], p2 = s[kf][2], p3 = s[kf][3];
                float x0 = __shfl_sync(0xffffffffu, p0, lA);
                float x1 = __shfl_sync(0xffffffffu, p1, lA);
                float y0 = __shfl_sync(0xffffffffu, p0, lB);
                float y1 = __shfl_sync(0xffffffffu, p1, lB);
                float z0 = __shfl_sync(0xffffffffu, p2, lA);
                float z1 = __shfl_sync(0xffffffffu, p3, lA);
                float w0 = __shfl_sync(0xffffffffu, p2, lB);
                float w1 = __shfl_sync(0xffffffffu, p3, lB);
                uint32_t a[4];
                a[0] = rna_tf32_bits(odd ? x1 : x0);
                a[1] = rna_tf32_bits(odd ? z1 : z0);
                a[2] = rna_tf32_bits(odd ? y1 : y0);
                a[3] = rna_tf32_bits(odd ? w1 : w0);
#pragma unroll
                for (int nf = 0; nf < 16; nf++) {
                    float2 bb = *(const float2*)(vbuf + ((kf * 16 + nf) * 32 + lane) * 2);
                    mma_tf32(o[nf], a,
                             __float_as_uint(bb.x), __float_as_uint(bb.y));
                }
            }
        }

        __syncthreads();
        if (kt + 2 < nkt) { stage(kt + 2, buf); CP_COMMIT(); }
    }

    const float il0 = 1.f / l0, il1 = 1.f / l1;
    const int b2 = bh >> 4, h2 = bh & 15;
    float* o0 = O + (size_t)(b2 * N + row0) * HD + h2 * A;
    float* o1 = O + (size_t)(b2 * N + row1) * HD + h2 * A;
#pragma unroll
    for (int nf = 0; nf < 16; nf++) {
        int col = nf * 8 + 2 * tig;
        *(float2*)(o0 + col) = make_float2(rna_tf32(o[nf][0] * il0),
                                           rna_tf32(o[nf][1] * il0));
        *(float2*)(o1 + col) = make_float2(rna_tf32(o[nf][2] * il1),
                                           rna_tf32(o[nf][3] * il1));
    }
}

// ---------------------------------------------------------------------------
extern "C" void kernel_launch(void* const* d_in, const int* in_sizes, int n_in,
                              void* d_out, int out_size) {
    const float* q  = (const float*)d_in[0];
    const float* Wq = (const float*)d_in[1];
    const float* Wk = (const float*)d_in[2];
    const float* Wv = (const float*)d_in[3];
    const float* Wo = (const float*)d_in[4];
    float* out = (float*)d_out;

    float *Qp, *Kp, *Vp, *AOp;
    cudaGetSymbolAddress((void**)&Qp,  g_Q);
    cudaGetSymbolAddress((void**)&Kp,  g_K);
    cudaGetSymbolAddress((void**)&Vp,  g_V);
    cudaGetSymbolAddress((void**)&AOp, g_AO);

    cudaFuncSetAttribute(qkv_gemm, cudaFuncAttributeMaxDynamicSharedMemorySize,
                         GEMM_SMEM);
    cudaFuncSetAttribute(out_gemm, cudaFuncAttributeMaxDynamicSharedMemorySize,
                         GEMM_SMEM);
    cudaFuncSetAttribute(attn_mma_kernel,
                         cudaFuncAttributeMaxDynamicSharedMemorySize, ATTN_SMEM);

    // fused QKV projections (rounding inlined in staging)
    qkv_gemm<<<dim3(16, 32, 3), 256, GEMM_SMEM>>>(q, Wq, Wk, Wv, Qp, Kp, Vp);

    // RoPE on Q and K
    int npairs = B * H * N * (A / 2);
    rope_kernel<<<npairs / 256, 256>>>(Qp, Kp);

    // tensor-core causal flash attention
    attn_mma_kernel<<<dim3(N / AQT, B * H), 256, ATTN_SMEM>>>(Qp, Kp, Vp, AOp);

    // output projection
    out_gemm<<<dim3(16, 32), 256, GEMM_SMEM>>>(AOp, Wo, out);
}

// round 6
// speedup vs baseline: 8.7795x; 1.7082x over previous
#include <cuda_runtime.h>
#include <cstdint>
#include <math.h>

// Problem constants
constexpr int B = 2;
constexpr int H = 16;
constexpr int N = 2048;
constexpr int A = 128;           // head dim
constexpr int W = 2048;          // model width
constexpr int HD = H * A;        // 2048
constexpr int Mdim = B * N;      // 4096
constexpr int Kdim = W;          // 2048

// Scratch (device globals — no allocation allowed)
__device__ float g_qr [Mdim * Kdim];     // tf32-rounded q
__device__ float g_Wqr[HD * W];
__device__ float g_Wkr[HD * W];
__device__ float g_Wvr[HD * W];
__device__ float g_Wor[W * HD];
__device__ float g_Q  [B * H * N * A];   // head-major
__device__ float g_K  [B * H * N * A];
__device__ float g_V  [B * H * N * A];
__device__ float g_AO [Mdim * HD];       // [b*n, h*a], rna-rounded by attention

// ---------------------------------------------------------------------------
// helpers
// ---------------------------------------------------------------------------
__device__ __forceinline__ float rna_tf32(float x) {
    uint32_t u;
    asm("cvt.rna.tf32.f32 %0, %1;" : "=r"(u) : "f"(x));
    return __uint_as_float(u);
}
__device__ __forceinline__ uint32_t rna_tf32_bits(float x) {
    uint32_t u;
    asm("cvt.rna.tf32.f32 %0, %1;" : "=r"(u) : "f"(x));
    return u;
}
__device__ __forceinline__ uint32_t smem_u32(const void* p) {
    uint32_t a;
    asm("{ .reg .u64 t; cvta.to.shared.u64 t, %1; cvt.u32.u64 %0, t; }"
        : "=r"(a) : "l"(p));
    return a;
}
__device__ __forceinline__ void mma_tf32(float* c, const uint32_t* a,
                                         uint32_t b0, uint32_t b1) {
    asm volatile(
        "mma.sync.aligned.m16n8k8.row.col.f32.tf32.tf32.f32 "
        "{%0,%1,%2,%3}, {%4,%5,%6,%7}, {%8,%9}, {%0,%1,%2,%3};"
        : "+f"(c[0]), "+f"(c[1]), "+f"(c[2]), "+f"(c[3])
        : "r"(a[0]), "r"(a[1]), "r"(a[2]), "r"(a[3]), "r"(b0), "r"(b1));
}
__device__ __forceinline__ void ldsm_x4(uint32_t* r, uint32_t addr) {
    asm volatile("ldmatrix.sync.aligned.m8n8.x4.shared.b16 {%0,%1,%2,%3}, [%4];"
                 : "=r"(r[0]), "=r"(r[1]), "=r"(r[2]), "=r"(r[3]) : "r"(addr));
}
#define CP_ASYNC4(dst, src) \
    asm volatile("cp.async.ca.shared.global [%0], [%1], 4;" :: "r"(dst), "l"(src))
#define CP_ASYNC16(dst, src) \
    asm volatile("cp.async.cg.shared.global [%0], [%1], 16;" :: "r"(dst), "l"(src))
#define CP_COMMIT() asm volatile("cp.async.commit_group;" ::: "memory")
#define CP_WAIT(n)  asm volatile("cp.async.wait_group %0;" :: "n"(n) : "memory")

// ---------------------------------------------------------------------------
// Fused rna-rounding pre-pass over q + 4 weights (single DRAM-bound launch).
// ---------------------------------------------------------------------------
constexpr int NQ4 = Mdim * Kdim / 4;   // 2,097,152
constexpr int NW4 = HD * W / 4;        // 1,048,576 = 2^20

__global__ void round_all_kernel(const float4* __restrict__ q,
                                 const float4* __restrict__ wq,
                                 const float4* __restrict__ wk,
                                 const float4* __restrict__ wv,
                                 const float4* __restrict__ wo,
                                 float4* __restrict__ qr,
                                 float4* __restrict__ wqr,
                                 float4* __restrict__ wkr,
                                 float4* __restrict__ wvr,
                                 float4* __restrict__ wor) {
    int i = blockIdx.x * blockDim.x + threadIdx.x;
    const float4* src;
    float4* dst;
    int off;
    if (i < NQ4) {
        src = q; dst = qr; off = i;
    } else {
        int j = i - NQ4;
        int w = j >> 20;
        off = j & (NW4 - 1);
        src = (w == 0) ? wq : (w == 1) ? wk : (w == 2) ? wv : wo;
        dst = (w == 0) ? wqr : (w == 1) ? wkr : (w == 2) ? wvr : wor;
    }
    float4 v = src[off];
    v.x = rna_tf32(v.x); v.y = rna_tf32(v.y);
    v.z = rna_tf32(v.z); v.w = rna_tf32(v.w);
    dst[off] = v;
}

// ---------------------------------------------------------------------------
// tf32 mma.sync GEMM: C[M,Nc] = A[M,K] @ B[Nc,K]^T (both K-contiguous, rna'd).
// 128x128 CTA tile, BK=32, 8 warps (4m x 2n), warp tile 32x64.
// 3-stage cp.async(16B) pipeline into XOR-swizzled row-major smem;
// fragments loaded via ldmatrix.x4. One syncthreads per k-tile.
// ---------------------------------------------------------------------------
constexpr int TILE_B     = 128 * 32 * 4;          // 16384 per operand
constexpr int STAGE_B    = 2 * TILE_B;            // 32768
constexpr int GEMM_SMEM  = 3 * STAGE_B;           // 98304

template <int SCATTER_C>
__device__ __forceinline__ void gemm_body(const float* __restrict__ Ag,
                                          const float* __restrict__ Bg,
                                          float* __restrict__ Cg) {
    extern __shared__ float gs[];
    const uint32_t sbase = smem_u32(gs);
    const int tid  = threadIdx.x;
    const int lane = tid & 31;
    const int wid  = tid >> 5;
    const int wm   = wid & 3;       // 32 rows each
    const int wn   = wid >> 2;      // 64 cols each
    const int m0   = blockIdx.y * 128;
    const int n0   = blockIdx.x * 128;

    float c[2][8][4];
#pragma unroll
    for (int mi = 0; mi < 2; mi++)
#pragma unroll
        for (int ni = 0; ni < 8; ni++)
#pragma unroll
            for (int j = 0; j < 4; j++) c[mi][ni][j] = 0.f;

    // staging: thread covers rows (tid>>3)+32i, 16B chunk (tid&7), both operands
    const int srow0 = tid >> 3;
    const int sc16  = tid & 7;
    auto stage = [&](int kt, int slot) {
        const uint32_t base = sbase + slot * STAGE_B;
        const float* Asrc = Ag + (size_t)(m0 + srow0) * Kdim + kt * 32 + sc16 * 4;
        const float* Bsrc = Bg + (size_t)(n0 + srow0) * Kdim + kt * 32 + sc16 * 4;
#pragma unroll
        for (int i = 0; i < 4; i++) {
            int row = srow0 + i * 32;
            uint32_t off = (uint32_t)row * 128 + ((sc16 ^ (row & 7)) << 4);
            CP_ASYNC16(base + off,          Asrc + (size_t)i * 32 * Kdim);
            CP_ASYNC16(base + TILE_B + off, Bsrc + (size_t)i * 32 * Kdim);
        }
    };

    // ldmatrix lane-address components
    const int a_row = wm * 32 + (lane & 15);            // + mi*16
    const int a_hi  = lane >> 4;                        // c16 low bit
    const int b_row = wn * 64 + (lane & 7) + ((lane >> 4) << 3);  // + nip*16
    const int b_hi  = (lane >> 3) & 1;

    stage(0, 0); CP_COMMIT();
    stage(1, 1); CP_COMMIT();

    constexpr int NKT = Kdim / 32;   // 64
    int slot = 0;
    for (int kt = 0; kt < NKT; kt++) {
        CP_WAIT(1);
        __syncthreads();
        // refill slot (kt+2)%3 == (kt-1)%3; its readers finished before the sync
        if (kt + 2 < NKT) {
            int ns = slot + 2; if (ns >= 3) ns -= 3;
            stage(kt + 2, ns);
        }
        CP_COMMIT();   // empty groups at the tail keep wait-counting consistent

        const uint32_t abase = sbase + slot * STAGE_B;
        const uint32_t bbase = abase + TILE_B;
#pragma unroll
        for (int ks = 0; ks < 4; ks++) {
            uint32_t af[2][4];
#pragma unroll
            for (int mi = 0; mi < 2; mi++) {
                int row = a_row + mi * 16;
                uint32_t addr = abase + (uint32_t)row * 128
                              + (((ks * 2 + a_hi) ^ (row & 7)) << 4);
                ldsm_x4(af[mi], addr);
            }
#pragma unroll
            for (int nip = 0; nip < 4; nip++) {
                int row = b_row + nip * 16;
                uint32_t addr = bbase + (uint32_t)row * 128
                              + (((ks * 2 + b_hi) ^ (row & 7)) << 4);
                uint32_t bf[4];
                ldsm_x4(bf, addr);
                mma_tf32(c[0][2 * nip],     af[0], bf[0], bf[1]);
                mma_tf32(c[1][2 * nip],     af[1], bf[0], bf[1]);
                mma_tf32(c[0][2 * nip + 1], af[0], bf[2], bf[3]);
                mma_tf32(c[1][2 * nip + 1], af[1], bf[2], bf[3]);
            }
        }
        slot++; if (slot >= 3) slot = 0;
    }

    const int gid = lane >> 2, tig = lane & 3;
#pragma unroll
    for (int mi = 0; mi < 2; mi++) {
#pragma unroll
        for (int ni = 0; ni < 8; ni++) {
            int n = n0 + wn * 64 + ni * 8 + tig * 2;
#pragma unroll
            for (int half = 0; half < 2; half++) {
                int m = m0 + wm * 32 + mi * 16 + gid + half * 8;
                float2 v = make_float2(c[mi][ni][half * 2], c[mi][ni][half * 2 + 1]);
                size_t dst;
                if (SCATTER_C) {
                    int b2 = m >> 11, np = m & 2047, h2 = n >> 7, a0 = n & 127;
                    dst = ((((size_t)b2 * H + h2) * N) + np) * A + a0;
                } else {
                    dst = (size_t)m * 2048 + n;
                }
                *(float2*)(Cg + dst) = v;
            }
        }
    }
}

__global__ __launch_bounds__(256, 2)
void qkv_gemm(const float* __restrict__ q,
              const float* __restrict__ Wq, const float* __restrict__ Wk,
              const float* __restrict__ Wv,
              float* __restrict__ Qp, float* __restrict__ Kp,
              float* __restrict__ Vp) {
    const int z = blockIdx.z;
    const float* Bg = (z == 0) ? Wq : (z == 1) ? Wk : Wv;
    float*       Cg = (z == 0) ? Qp : (z == 1) ? Kp : Vp;
    gemm_body<1>(q, Bg, Cg);
}

__global__ __launch_bounds__(256, 2)
void out_gemm(const float* __restrict__ Ag, const float* __restrict__ Bg,
              float* __restrict__ Cg) {
    gemm_body<0>(Ag, Bg, Cg);
}

// ---------------------------------------------------------------------------
// RoPE (interleaved pairs), in place on Q and K (head-major layout).
// ---------------------------------------------------------------------------
__global__ void rope_kernel(float* __restrict__ Q, float* __restrict__ K) {
    int idx = blockIdx.x * blockDim.x + threadIdx.x;
    int i = idx & 63;
    int npos = (idx >> 6) & 2047;
    float freq = __powf(10000.0f, -(float)i * (1.0f / 63.0f));
    float th = (float)npos * freq;
    float s, c;
    sincosf(th, &s, &c);
    size_t base = (size_t)idx * 2;

    float q0 = Q[base], q1 = Q[base + 1];
    Q[base]     = q0 * c - q1 * s;
    Q[base + 1] = q1 * c + q0 * s;

    float k0 = K[base], k1 = K[base + 1];
    K[base]     = k0 * c - k1 * s;
    K[base + 1] = k1 * c + k0 * s;
}

// ---------------------------------------------------------------------------
// Tensor-core causal flash attention (tf32 mma.sync). Unchanged from R4/R5.
// ---------------------------------------------------------------------------
constexpr int AQT = 128;
constexpr int AKT = 64;
constexpr int QS_FLOATS = AQT * 128;
constexpr int KT_FLOATS = AKT * 128;
constexpr int ATTN_SMEM = (QS_FLOATS + 4 * KT_FLOATS) * 4;  // 196608 B

__global__ __launch_bounds__(256, 1)
void attn_mma_kernel(const float* __restrict__ Q, const float* __restrict__ K,
                     const float* __restrict__ V, float* __restrict__ O) {
    extern __shared__ float smx[];
    float* Qs = smx;
    float* Ks = smx + QS_FLOATS;
    float* Vs = smx + QS_FLOATS + 2 * KT_FLOATS;

    const int tid  = threadIdx.x;
    const int lane = tid & 31;
    const int wid  = tid >> 5;
    const int gid  = lane >> 2, tig = lane & 3;
    const int bh   = blockIdx.y;
    const int qt   = gridDim.x - 1 - blockIdx.x;
    const int q0   = qt * AQT;

    const float* Qb = Q + (size_t)bh * N * A;
    const float* Kb = K + (size_t)bh * N * A;
    const float* Vb = V + (size_t)bh * N * A;

    const float scl = 0.08838834764831845f;   // 1/sqrt(128)
#pragma unroll
    for (int i = 0; i < 16; i++) {
        int idx = tid + i * 256;
        int row = idx >> 5, c4 = idx & 31;
        float4 v = *(const float4*)(Qb + (size_t)(q0 + row) * A + c4 * 4);
        int w = row >> 4, r = row & 15, kf = c4 >> 1;
        int rg = ((r >> 3) & 1) | ((c4 & 1) << 1);
        float* dst = Qs + (w * 16 + kf) * 128 + ((r & 7) * 4) * 4 + rg;
        dst[0]  = rna_tf32(v.x * scl);
        dst[4]  = rna_tf32(v.y * scl);
        dst[8]  = rna_tf32(v.z * scl);
        dst[12] = rna_tf32(v.w * scl);
    }
    __syncthreads();

    uint32_t qf[16][4];
#pragma unroll
    for (int kd = 0; kd < 16; kd++) {
        float4 t = *(const float4*)(Qs + (wid * 16 + kd) * 128 + lane * 4);
        qf[kd][0] = __float_as_uint(t.x);
        qf[kd][1] = __float_as_uint(t.y);
        qf[kd][2] = __float_as_uint(t.z);
        qf[kd][3] = __float_as_uint(t.w);
    }

    const uint32_t ks_base = smem_u32(Ks);
    const uint32_t vs_base = smem_u32(Vs);
    const int sd   = tid & 127;
    const int key0 = tid >> 7;
    const int s_kd  = sd >> 3;
    const int s_d3  = sd & 3;
    const int s_rgk = (sd >> 2) & 1;
    const int s_ln7 = (sd & 7) * 4;

    auto stage = [&](int kt, int buf) {
        const float* Kg = Kb + (size_t)(kt * AKT) * A + sd;
        const float* Vg = Vb + (size_t)(kt * AKT) * A + sd;
        uint32_t kb = ks_base + buf * (KT_FLOATS * 4);
        uint32_t vb = vs_base + buf * (KT_FLOATS * 4);
#pragma unroll
        for (int i = 0; i < 32; i++) {
            int key = key0 + 2 * i;
            int nk  = key >> 3;
            int lnk = (key & 7) * 4 + s_d3;
            uint32_t ka = kb + (((s_kd * 8 + nk) * 32 + lnk) * 2 + s_rgk) * 4;
            CP_ASYNC4(ka, Kg + key * 128);
            int kfv = key >> 3;
            int lnv = s_ln7 + (key & 3);
            int rgv = (key >> 2) & 1;
            uint32_t va = vb + (((kfv * 16 + s_kd) * 32 + lnv) * 2 + rgv) * 4;
            CP_ASYNC4(va, Vg + key * 128);
        }
    };

    const int nkt  = 2 * qt + 2;
    const int nktw = 2 * qt + 1 + (wid >> 2);

    float o[16][4];
#pragma unroll
    for (int nf = 0; nf < 16; nf++)
#pragma unroll
        for (int j = 0; j < 4; j++) o[nf][j] = 0.f;
    float m0 = -1e30f, m1 = -1e30f, l0 = 0.f, l1 = 0.f;

    const int row0 = q0 + wid * 16 + gid;
    const int row1 = row0 + 8;

    stage(0, 0); CP_COMMIT();
    stage(1, 1); CP_COMMIT();

    for (int kt = 0; kt < nkt; kt++) {
        const int buf = kt & 1;
        if (kt < nkt - 1) { CP_WAIT(1); } else { CP_WAIT(0); }
        __syncthreads();

        if (kt < nktw) {
            const float* kbuf = Ks + buf * KT_FLOATS;
            const float* vbuf = Vs + buf * KT_FLOATS;

            float s[8][4];
#pragma unroll
            for (int nk = 0; nk < 8; nk++)
#pragma unroll
                for (int j = 0; j < 4; j++) s[nk][j] = 0.f;

#pragma unroll
            for (int kd = 0; kd < 16; kd++) {
#pragma unroll
                for (int nk = 0; nk < 8; nk++) {
                    float2 bb = *(const float2*)(kbuf + ((kd * 8 + nk) * 32 + lane) * 2);
                    mma_tf32(s[nk], qf[kd],
                             __float_as_uint(bb.x), __float_as_uint(bb.y));
                }
            }

            if (kt == nktw - 1) {
                int colb = kt * AKT + 2 * tig;
#pragma unroll
                for (int nk = 0; nk < 8; nk++) {
                    int c0 = colb + nk * 8;
                    if (c0     > row0) s[nk][0] = -1e30f;
                    if (c0 + 1 > row0) s[nk][1] = -1e30f;
                    if (c0     > row1) s[nk][2] = -1e30f;
                    if (c0 + 1 > row1) s[nk][3] = -1e30f;
                }
            }

            float mx0 = -1e30f, mx1 = -1e30f;
#pragma unroll
            for (int nk = 0; nk < 8; nk++) {
                mx0 = fmaxf(mx0, fmaxf(s[nk][0], s[nk][1]));
                mx1 = fmaxf(mx1, fmaxf(s[nk][2], s[nk][3]));
            }
            mx0 = fmaxf(mx0, __shfl_xor_sync(0xffffffffu, mx0, 1));
            mx0 = fmaxf(mx0, __shfl_xor_sync(0xffffffffu, mx0, 2));
            mx1 = fmaxf(mx1, __shfl_xor_sync(0xffffffffu, mx1, 1));
            mx1 = fmaxf(mx1, __shfl_xor_sync(0xffffffffu, mx1, 2));
            float mn0 = fmaxf(m0, mx0), mn1 = fmaxf(m1, mx1);
            float cor0 = __expf(m0 - mn0), cor1 = __expf(m1 - mn1);
            m0 = mn0; m1 = mn1;

            float rs0 = 0.f, rs1 = 0.f;
#pragma unroll
            for (int nk = 0; nk < 8; nk++) {
                s[nk][0] = __expf(s[nk][0] - mn0);
                s[nk][1] = __expf(s[nk][1] - mn0);
                s[nk][2] = __expf(s[nk][2] - mn1);
                s[nk][3] = __expf(s[nk][3] - mn1);
                rs0 += s[nk][0] + s[nk][1];
                rs1 += s[nk][2] + s[nk][3];
            }
            rs0 += __shfl_xor_sync(0xffffffffu, rs0, 1);
            rs0 += __shfl_xor_sync(0xffffffffu, rs0, 2);
            rs1 += __shfl_xor_sync(0xffffffffu, rs1, 1);
            rs1 += __shfl_xor_sync(0xffffffffu, rs1, 2);
            l0 = l0 * cor0 + rs0;
            l1 = l1 * cor1 + rs1;

#pragma unroll
            for (int nf = 0; nf < 16; nf++) {
                o[nf][0] *= cor0; o[nf][1] *= cor0;
                o[nf][2] *= cor1; o[nf][3] *= cor1;
            }

            const int lA = (gid << 2) + (tig >> 1);
            const int lB = lA + 2;
            const bool odd = tig & 1;
#pragma unroll
            for (int kf = 0; kf < 8; kf++) {
                float p0 = s[kf][0], p1 = s[kf][1], p2 = s[kf][2], p3 = s[kf][3];
                float x0 = __shfl_sync(0xffffffffu, p0, lA);
                float x1 = __shfl_sync(0xffffffffu, p1, lA);
                float y0 = __shfl_sync(0xffffffffu, p0, lB);
                float y1 = __shfl_sync(0xffffffffu, p1, lB);
                float z0 = __shfl_sync(0xffffffffu, p2, lA);
                float z1 = __shfl_sync(0xffffffffu, p3, lA);
                float w0 = __shfl_sync(0xffffffffu, p2, lB);
                float w1 = __shfl_sync(0xffffffffu, p3, lB);
                uint32_t a[4];
                a[0] = rna_tf32_bits(odd ? x1 : x0);
                a[1] = rna_tf32_bits(odd ? z1 : z0);
                a[2] = rna_tf32_bits(odd ? y1 : y0);
                a[3] = rna_tf32_bits(odd ? w1 : w0);
#pragma unroll
                for (int nf = 0; nf < 16; nf++) {
                    float2 bb = *(const float2*)(vbuf + ((kf * 16 + nf) * 32 + lane) * 2);
                    mma_tf32(o[nf], a,
                             __float_as_uint(bb.x), __float_as_uint(bb.y));
                }
            }
        }

        __syncthreads();
        if (kt + 2 < nkt) { stage(kt + 2, buf); CP_COMMIT(); }
    }

    const float il0 = 1.f / l0, il1 = 1.f / l1;
    const int b2 = bh >> 4, h2 = bh & 15;
    float* o0 = O + (size_t)(b2 * N + row0) * HD + h2 * A;
    float* o1 = O + (size_t)(b2 * N + row1) * HD + h2 * A;
#pragma unroll
    for (int nf = 0; nf < 16; nf++) {
        int col = nf * 8 + 2 * tig;
        *(float2*)(o0 + col) = make_float2(rna_tf32(o[nf][0] * il0),
                                           rna_tf32(o[nf][1] * il0));
        *(float2*)(o1 + col) = make_float2(rna_tf32(o[nf][2] * il1),
                                           rna_tf32(o[nf][3] * il1));
    }
}

// ---------------------------------------------------------------------------
extern "C" void kernel_launch(void* const* d_in, const int* in_sizes, int n_in,
                              void* d_out, int out_size) {
    const float* q  = (const float*)d_in[0];
    const float* Wq = (const float*)d_in[1];
    const float* Wk = (const float*)d_in[2];
    const float* Wv = (const float*)d_in[3];
    const float* Wo = (const float*)d_in[4];
    float* out = (float*)d_out;

    float *qr, *Wqr, *Wkr, *Wvr, *Wor, *Qp, *Kp, *Vp, *AOp;
    cudaGetSymbolAddress((void**)&qr,  g_qr);
    cudaGetSymbolAddress((void**)&Wqr, g_Wqr);
    cudaGetSymbolAddress((void**)&Wkr, g_Wkr);
    cudaGetSymbolAddress((void**)&Wvr, g_Wvr);
    cudaGetSymbolAddress((void**)&Wor, g_Wor);
    cudaGetSymbolAddress((void**)&Qp,  g_Q);
    cudaGetSymbolAddress((void**)&Kp,  g_K);
    cudaGetSymbolAddress((void**)&Vp,  g_V);
    cudaGetSymbolAddress((void**)&AOp, g_AO);

    cudaFuncSetAttribute(qkv_gemm, cudaFuncAttributeMaxDynamicSharedMemorySize,
                         GEMM_SMEM);
    cudaFuncSetAttribute(out_gemm, cudaFuncAttributeMaxDynamicSharedMemorySize,
                         GEMM_SMEM);
    cudaFuncSetAttribute(attn_mma_kernel,
                         cudaFuncAttributeMaxDynamicSharedMemorySize, ATTN_SMEM);

    // fused rna pre-pass (q + 4 weights)
    {
        int total = NQ4 + 4 * NW4;   // 6,291,456
        round_all_kernel<<<total / 256, 256>>>(
            (const float4*)q, (const float4*)Wq, (const float4*)Wk,
            (const float4*)Wv, (const float4*)Wo,
            (float4*)qr, (float4*)Wqr, (float4*)Wkr, (float4*)Wvr, (float4*)Wor);
    }

    // fused QKV projections
    qkv_gemm<<<dim3(16, 32, 3), 256, GEMM_SMEM>>>(qr, Wqr, Wkr, Wvr, Qp, Kp, Vp);

    // RoPE on Q and K
    int npairs = B * H * N * (A / 2);
    rope_kernel<<<npairs / 256, 256>>>(Qp, Kp);

    // tensor-core causal flash attention
    attn_mma_kernel<<<dim3(N / AQT, B * H), 256, ATTN_SMEM>>>(Qp, Kp, Vp, AOp);

    // output projection
    out_gemm<<<dim3(16, 32), 256, GEMM_SMEM>>>(AOp, Wor, out);
}

// round 7
// speedup vs baseline: 8.8352x; 1.0063x over previous
#include <cuda_runtime.h>
#include <cstdint>
#include <math.h>

// Problem constants
constexpr int B = 2;
constexpr int H = 16;
constexpr int N = 2048;
constexpr int A = 128;           // head dim
constexpr int W = 2048;          // model width
constexpr int HD = H * A;        // 2048
constexpr int Mdim = B * N;      // 4096
constexpr int Kdim = W;          // 2048

// Scratch (device globals — no allocation allowed)
__device__ float g_qr [Mdim * Kdim];     // tf32-rounded q
__device__ float g_Wqr[HD * W];
__device__ float g_Wkr[HD * W];
__device__ float g_Wvr[HD * W];
__device__ float g_Wor[W * HD];
__device__ float g_Q  [B * H * N * A];   // head-major
__device__ float g_K  [B * H * N * A];
__device__ float g_V  [B * H * N * A];
__device__ float g_AO [Mdim * HD];       // [b*n, h*a], rna-rounded by attention

// ---------------------------------------------------------------------------
// helpers
// ---------------------------------------------------------------------------
__device__ __forceinline__ float rna_tf32(float x) {
    uint32_t u;
    asm("cvt.rna.tf32.f32 %0, %1;" : "=r"(u) : "f"(x));
    return __uint_as_float(u);
}
__device__ __forceinline__ uint32_t rna_tf32_bits(float x) {
    uint32_t u;
    asm("cvt.rna.tf32.f32 %0, %1;" : "=r"(u) : "f"(x));
    return u;
}
__device__ __forceinline__ uint32_t smem_u32(const void* p) {
    uint32_t a;
    asm("{ .reg .u64 t; cvta.to.shared.u64 t, %1; cvt.u32.u64 %0, t; }"
        : "=r"(a) : "l"(p));
    return a;
}
__device__ __forceinline__ void mma_tf32(float* c, const uint32_t* a,
                                         uint32_t b0, uint32_t b1) {
    asm volatile(
        "mma.sync.aligned.m16n8k8.row.col.f32.tf32.tf32.f32 "
        "{%0,%1,%2,%3}, {%4,%5,%6,%7}, {%8,%9}, {%0,%1,%2,%3};"
        : "+f"(c[0]), "+f"(c[1]), "+f"(c[2]), "+f"(c[3])
        : "r"(a[0]), "r"(a[1]), "r"(a[2]), "r"(a[3]), "r"(b0), "r"(b1));
}
__device__ __forceinline__ void ldsm_x4(uint32_t* r, uint32_t addr) {
    asm volatile("ldmatrix.sync.aligned.m8n8.x4.shared.b16 {%0,%1,%2,%3}, [%4];"
                 : "=r"(r[0]), "=r"(r[1]), "=r"(r[2]), "=r"(r[3]) : "r"(addr));
}
#define CP_ASYNC4(dst, src) \
    asm volatile("cp.async.ca.shared.global [%0], [%1], 4;" :: "r"(dst), "l"(src))
#define CP_ASYNC16(dst, src) \
    asm volatile("cp.async.cg.shared.global [%0], [%1], 16;" :: "r"(dst), "l"(src))
#define CP_COMMIT() asm volatile("cp.async.commit_group;" ::: "memory")
#define CP_WAIT(n)  asm volatile("cp.async.wait_group %0;" :: "n"(n) : "memory")

// ---------------------------------------------------------------------------
// Fused rna-rounding pre-pass over q + 4 weights (single DRAM-bound launch).
// ---------------------------------------------------------------------------
constexpr int NQ4 = Mdim * Kdim / 4;   // 2,097,152
constexpr int NW4 = HD * W / 4;        // 1,048,576 = 2^20

__global__ void round_all_kernel(const float4* __restrict__ q,
                                 const float4* __restrict__ wq,
                                 const float4* __restrict__ wk,
                                 const float4* __restrict__ wv,
                                 const float4* __restrict__ wo,
                                 float4* __restrict__ qr,
                                 float4* __restrict__ wqr,
                                 float4* __restrict__ wkr,
                                 float4* __restrict__ wvr,
                                 float4* __restrict__ wor) {
    int i = blockIdx.x * blockDim.x + threadIdx.x;
    const float4* src;
    float4* dst;
    int off;
    if (i < NQ4) {
        src = q; dst = qr; off = i;
    } else {
        int j = i - NQ4;
        int w = j >> 20;
        off = j & (NW4 - 1);
        src = (w == 0) ? wq : (w == 1) ? wk : (w == 2) ? wv : wo;
        dst = (w == 0) ? wqr : (w == 1) ? wkr : (w == 2) ? wvr : wor;
    }
    float4 v = src[off];
    v.x = rna_tf32(v.x); v.y = rna_tf32(v.y);
    v.z = rna_tf32(v.z); v.w = rna_tf32(v.w);
    dst[off] = v;
}

// ---------------------------------------------------------------------------
// tf32 mma.sync GEMM (unchanged from R6): 128x128 CTA, BK=32, ldmatrix,
// 3-stage cp.async pipeline, XOR-swizzled row-major smem.
// ---------------------------------------------------------------------------
constexpr int TILE_B     = 128 * 32 * 4;          // 16384 per operand
constexpr int STAGE_B    = 2 * TILE_B;            // 32768
constexpr int GEMM_SMEM  = 3 * STAGE_B;           // 98304

template <int SCATTER_C>
__device__ __forceinline__ void gemm_body(const float* __restrict__ Ag,
                                          const float* __restrict__ Bg,
                                          float* __restrict__ Cg) {
    extern __shared__ float gs[];
    const uint32_t sbase = smem_u32(gs);
    const int tid  = threadIdx.x;
    const int lane = tid & 31;
    const int wid  = tid >> 5;
    const int wm   = wid & 3;
    const int wn   = wid >> 2;
    const int m0   = blockIdx.y * 128;
    const int n0   = blockIdx.x * 128;

    float c[2][8][4];
#pragma unroll
    for (int mi = 0; mi < 2; mi++)
#pragma unroll
        for (int ni = 0; ni < 8; ni++)
#pragma unroll
            for (int j = 0; j < 4; j++) c[mi][ni][j] = 0.f;

    const int srow0 = tid >> 3;
    const int sc16  = tid & 7;
    auto stage = [&](int kt, int slot) {
        const uint32_t base = sbase + slot * STAGE_B;
        const float* Asrc = Ag + (size_t)(m0 + srow0) * Kdim + kt * 32 + sc16 * 4;
        const float* Bsrc = Bg + (size_t)(n0 + srow0) * Kdim + kt * 32 + sc16 * 4;
#pragma unroll
        for (int i = 0; i < 4; i++) {
            int row = srow0 + i * 32;
            uint32_t off = (uint32_t)row * 128 + ((sc16 ^ (row & 7)) << 4);
            CP_ASYNC16(base + off,          Asrc + (size_t)i * 32 * Kdim);
            CP_ASYNC16(base + TILE_B + off, Bsrc + (size_t)i * 32 * Kdim);
        }
    };

    const int a_row = wm * 32 + (lane & 15);
    const int a_hi  = lane >> 4;
    const int b_row = wn * 64 + (lane & 7) + ((lane >> 4) << 3);
    const int b_hi  = (lane >> 3) & 1;

    stage(0, 0); CP_COMMIT();
    stage(1, 1); CP_COMMIT();

    constexpr int NKT = Kdim / 32;
    int slot = 0;
    for (int kt = 0; kt < NKT; kt++) {
        CP_WAIT(1);
        __syncthreads();
        if (kt + 2 < NKT) {
            int ns = slot + 2; if (ns >= 3) ns -= 3;
            stage(kt + 2, ns);
        }
        CP_COMMIT();

        const uint32_t abase = sbase + slot * STAGE_B;
        const uint32_t bbase = abase + TILE_B;
#pragma unroll
        for (int ks = 0; ks < 4; ks++) {
            uint32_t af[2][4];
#pragma unroll
            for (int mi = 0; mi < 2; mi++) {
                int row = a_row + mi * 16;
                uint32_t addr = abase + (uint32_t)row * 128
                              + (((ks * 2 + a_hi) ^ (row & 7)) << 4);
                ldsm_x4(af[mi], addr);
            }
#pragma unroll
            for (int nip = 0; nip < 4; nip++) {
                int row = b_row + nip * 16;
                uint32_t addr = bbase + (uint32_t)row * 128
                              + (((ks * 2 + b_hi) ^ (row & 7)) << 4);
                uint32_t bf[4];
                ldsm_x4(bf, addr);
                mma_tf32(c[0][2 * nip],     af[0], bf[0], bf[1]);
                mma_tf32(c[1][2 * nip],     af[1], bf[0], bf[1]);
                mma_tf32(c[0][2 * nip + 1], af[0], bf[2], bf[3]);
                mma_tf32(c[1][2 * nip + 1], af[1], bf[2], bf[3]);
            }
        }
        slot++; if (slot >= 3) slot = 0;
    }

    const int gid = lane >> 2, tig = lane & 3;
#pragma unroll
    for (int mi = 0; mi < 2; mi++) {
#pragma unroll
        for (int ni = 0; ni < 8; ni++) {
            int n = n0 + wn * 64 + ni * 8 + tig * 2;
#pragma unroll
            for (int half = 0; half < 2; half++) {
                int m = m0 + wm * 32 + mi * 16 + gid + half * 8;
                float2 v = make_float2(c[mi][ni][half * 2], c[mi][ni][half * 2 + 1]);
                size_t dst;
                if (SCATTER_C) {
                    int b2 = m >> 11, np = m & 2047, h2 = n >> 7, a0 = n & 127;
                    dst = ((((size_t)b2 * H + h2) * N) + np) * A + a0;
                } else {
                    dst = (size_t)m * 2048 + n;
                }
                *(float2*)(Cg + dst) = v;
            }
        }
    }
}

__global__ __launch_bounds__(256, 2)
void qkv_gemm(const float* __restrict__ q,
              const float* __restrict__ Wq, const float* __restrict__ Wk,
              const float* __restrict__ Wv,
              float* __restrict__ Qp, float* __restrict__ Kp,
              float* __restrict__ Vp) {
    const int z = blockIdx.z;
    const float* Bg = (z == 0) ? Wq : (z == 1) ? Wk : Wv;
    float*       Cg = (z == 0) ? Qp : (z == 1) ? Kp : Vp;
    gemm_body<1>(q, Bg, Cg);
}

__global__ __launch_bounds__(256, 2)
void out_gemm(const float* __restrict__ Ag, const float* __restrict__ Bg,
              float* __restrict__ Cg) {
    gemm_body<0>(Ag, Bg, Cg);
}

// ---------------------------------------------------------------------------
// RoPE (interleaved pairs), in place on Q and K (head-major layout).
// ---------------------------------------------------------------------------
__global__ void rope_kernel(float* __restrict__ Q, float* __restrict__ K) {
    int idx = blockIdx.x * blockDim.x + threadIdx.x;
    int i = idx & 63;
    int npos = (idx >> 6) & 2047;
    float freq = __powf(10000.0f, -(float)i * (1.0f / 63.0f));
    float th = (float)npos * freq;
    float s, c;
    sincosf(th, &s, &c);
    size_t base = (size_t)idx * 2;

    float q0 = Q[base], q1 = Q[base + 1];
    Q[base]     = q0 * c - q1 * s;
    Q[base + 1] = q1 * c + q0 * s;

    float k0 = K[base], k1 = K[base + 1];
    K[base]     = k0 * c - k1 * s;
    K[base + 1] = k1 * c + k0 * s;
}

// ---------------------------------------------------------------------------
// Tensor-core causal flash attention, v2.
// CTA: 64 queries, 128 threads (4 warps, 16 q-rows each), K tile 32 keys.
// K: row-major XOR-swizzled smem (16B cp.async) + ldmatrix.x4.
// V: frag-order smem (4B cp.async) + lds.64 (cp.async cannot transpose).
// Q: staged via smem alias of KV stage 0, then register-resident A-frags.
// smem = 64KB -> 2 CTAs/SM.
// ---------------------------------------------------------------------------
constexpr int AQT = 64;
constexpr int AKT = 32;
constexpr int K_TILE_B  = AKT * 128 * 4;          // 16384 B
constexpr int STAGE_F   = AKT * 128 * 2;          // 8192 floats (K + V)
constexpr int ATTN_SMEM = 2 * STAGE_F * 4;        // 65536 B

__global__ __launch_bounds__(128)
void attn_mma_kernel(const float* __restrict__ Q, const float* __restrict__ K,
                     const float* __restrict__ V, float* __restrict__ O) {
    extern __shared__ float smx[];
    const uint32_t sbase = smem_u32(smx);

    const int tid  = threadIdx.x;
    const int lane = tid & 31;
    const int wid  = tid >> 5;          // 0..3
    const int gid  = lane >> 2, tig = lane & 3;
    const int bh   = blockIdx.y;
    const int qt   = gridDim.x - 1 - blockIdx.x;   // heavy tiles first
    const int q0   = qt * AQT;

    const float* Qb = Q + (size_t)bh * N * A;
    const float* Kb = K + (size_t)bh * N * A;
    const float* Vb = V + (size_t)bh * N * A;

    // ---- stage Q (64 rows x 512B) row-major swizzled into stage-0 alias ----
    {
        const int c16 = tid & 31;
        const int r0  = tid >> 5;       // 0..3
#pragma unroll
        for (int i = 0; i < 16; i++) {
            int row = r0 + i * 4;
            uint32_t off = (uint32_t)row * 512 + ((c16 ^ (row & 7)) << 4);
            CP_ASYNC16(sbase + off, Qb + (size_t)(q0 + row) * A + c16 * 4);
        }
        CP_COMMIT();
        CP_WAIT(0);
        __syncthreads();
    }

    // ---- Q A-frags -> registers (scale + rna) ----
    const float scl = 0.08838834764831845f;   // 1/sqrt(128)
    uint32_t qf[16][4];
    {
        const int a_row = wid * 16 + (lane & 15);
        const int a_hi  = lane >> 4;
#pragma unroll
        for (int kd = 0; kd < 16; kd++) {
            uint32_t addr = sbase + (uint32_t)a_row * 512
                          + (((kd * 2 + a_hi) ^ (a_row & 7)) << 4);
            ldsm_x4(qf[kd], addr);
#pragma unroll
            for (int j = 0; j < 4; j++)
                qf[kd][j] = rna_tf32_bits(__uint_as_float(qf[kd][j]) * scl);
        }
    }
    __syncthreads();   // Q smem now reusable as KV stage 0

    // ---- KV staging ----
    const int s_c16 = tid & 31;
    const int s_r0  = tid >> 5;
    const int v_nf  = tid >> 3;           // d>>3
    const int v_ln7 = (tid & 7) * 4;
    auto stage = [&](int kt, int slot) {
        const uint32_t kb = sbase + slot * (STAGE_F * 4);
        const uint32_t vb = kb + K_TILE_B;
        const float* Kg = Kb + (size_t)(kt * AKT) * A;
        const float* Vg = Vb + (size_t)(kt * AKT) * A + tid;   // column d=tid
#pragma unroll
        for (int i = 0; i < 8; i++) {
            int row = s_r0 + i * 4;
            uint32_t off = (uint32_t)row * 512 + ((s_c16 ^ (row & 7)) << 4);
            CP_ASYNC16(kb + off, Kg + (size_t)row * A + s_c16 * 4);
        }
#pragma unroll
        for (int key = 0; key < 32; key++) {
            int kfv = key >> 3;
            int lnv = v_ln7 + (key & 3);
            int rgv = (key >> 2) & 1;
            uint32_t va = vb + ((((kfv * 16 + v_nf) * 32 + lnv) * 2 + rgv) << 2);
            CP_ASYNC4(va, Vg + (size_t)key * A);
        }
    };

    const int nkt  = 2 * qt + 2;                 // 32-key tiles (CTA)
    const int nktw = 2 * qt + (wid >> 1) + 1;    // this warp's tiles

    float o[16][4];
#pragma unroll
    for (int nf = 0; nf < 16; nf++)
#pragma unroll
        for (int j = 0; j < 4; j++) o[nf][j] = 0.f;
    float m0 = -1e30f, m1 = -1e30f, l0 = 0.f, l1 = 0.f;

    const int row0 = q0 + wid * 16 + gid;
    const int row1 = row0 + 8;
    const int b_row = (lane & 7) + ((lane >> 4) << 3);   // 0..15
    const int b_hi  = (lane >> 3) & 1;

    stage(0, 0); CP_COMMIT();
    stage(1, 1); CP_COMMIT();

    for (int kt = 0; kt < nkt; kt++) {
        const int buf = kt & 1;
        if (kt < nkt - 1) { CP_WAIT(1); } else { CP_WAIT(0); }
        __syncthreads();

        if (kt < nktw) {
            const uint32_t kbase = sbase + buf * (STAGE_F * 4);
            const float*   vbuf  = smx + buf * STAGE_F + AKT * 128;

            // ---- S = Q K^T (32 keys = 4 n-groups) ----
            float s[4][4];
#pragma unroll
            for (int nk = 0; nk < 4; nk++)
#pragma unroll
                for (int j = 0; j < 4; j++) s[nk][j] = 0.f;

#pragma unroll
            for (int kd = 0; kd < 16; kd++) {
                uint32_t col = ((kd * 2 + b_hi) ^ (b_row & 7)) << 4;
                uint32_t bf0[4], bf1[4];
                ldsm_x4(bf0, kbase + (uint32_t)b_row * 512 + col);
                ldsm_x4(bf1, kbase + (uint32_t)(b_row + 16) * 512 + col);
                mma_tf32(s[0], qf[kd], bf0[0], bf0[1]);
                mma_tf32(s[1], qf[kd], bf0[2], bf0[3]);
                mma_tf32(s[2], qf[kd], bf1[0], bf1[1]);
                mma_tf32(s[3], qf[kd], bf1[2], bf1[3]);
            }

            // ---- causal mask (diagonal tile only) ----
            if (kt == nktw - 1) {
                int colb = kt * AKT + 2 * tig;
#pragma unroll
                for (int nk = 0; nk < 4; nk++) {
                    int c0 = colb + nk * 8;
                    if (c0     > row0) s[nk][0] = -1e30f;
                    if (c0 + 1 > row0) s[nk][1] = -1e30f;
                    if (c0     > row1) s[nk][2] = -1e30f;
                    if (c0 + 1 > row1) s[nk][3] = -1e30f;
                }
            }

            // ---- online softmax ----
            float mx0 = -1e30f, mx1 = -1e30f;
#pragma unroll
            for (int nk = 0; nk < 4; nk++) {
                mx0 = fmaxf(mx0, fmaxf(s[nk][0], s[nk][1]));
                mx1 = fmaxf(mx1, fmaxf(s[nk][2], s[nk][3]));
            }
            mx0 = fmaxf(mx0, __shfl_xor_sync(0xffffffffu, mx0, 1));
            mx0 = fmaxf(mx0, __shfl_xor_sync(0xffffffffu, mx0, 2));
            mx1 = fmaxf(mx1, __shfl_xor_sync(0xffffffffu, mx1, 1));
            mx1 = fmaxf(mx1, __shfl_xor_sync(0xffffffffu, mx1, 2));
            float mn0 = fmaxf(m0, mx0), mn1 = fmaxf(m1, mx1);
            float cor0 = __expf(m0 - mn0), cor1 = __expf(m1 - mn1);
            m0 = mn0; m1 = mn1;

            float rs0 = 0.f, rs1 = 0.f;
#pragma unroll
            for (int nk = 0; nk < 4; nk++) {
                s[nk][0] = __expf(s[nk][0] - mn0);
                s[nk][1] = __expf(s[nk][1] - mn0);
                s[nk][2] = __expf(s[nk][2] - mn1);
                s[nk][3] = __expf(s[nk][3] - mn1);
                rs0 += s[nk][0] + s[nk][1];
                rs1 += s[nk][2] + s[nk][3];
            }
            rs0 += __shfl_xor_sync(0xffffffffu, rs0, 1);
            rs0 += __shfl_xor_sync(0xffffffffu, rs0, 2);
            rs1 += __shfl_xor_sync(0xffffffffu, rs1, 1);
            rs1 += __shfl_xor_sync(0xffffffffu, rs1, 2);
            l0 = l0 * cor0 + rs0;
            l1 = l1 * cor1 + rs1;

#pragma unroll
            for (int nf = 0; nf < 16; nf++) {
                o[nf][0] *= cor0; o[nf][1] *= cor0;
                o[nf][2] *= cor1; o[nf][3] *= cor1;
            }

            // ---- O += P V : P C-layout -> A-frag via quad shuffles ----
            const int lA = (gid << 2) + (tig >> 1);
            const int lB = lA + 2;
            const bool odd = tig & 1;
#pragma unroll
            for (int kf = 0; kf < 4; kf++) {
                float p0 = s[kf][0], p1 = s[kf][1], p2 = s[kf][2], p3 = s[kf][3];
                float x0 = __shfl_sync(0xffffffffu, p0, lA);
                float x1 = __shfl_sync(0xffffffffu, p1, lA);
                float y0 = __shfl_sync(0xffffffffu, p0, lB);
                float y1 = __shfl_sync(0xffffffffu, p1, lB);
                float z0 = __shfl_sync(0xffffffffu, p2, lA);
                float z1 = __shfl_sync(0xffffffffu, p3, lA);
                float w0 = __shfl_sync(0xffffffffu, p2, lB);
                float w1 = __shfl_sync(0xffffffffu, p3, lB);
                uint32_t a[4];
                a[0] = rna_tf32_bits(odd ? x1 : x0);
                a[1] = rna_tf32_bits(odd ? z1 : z0);
                a[2] = rna_tf32_bits(odd ? y1 : y0);
                a[3] = rna_tf32_bits(odd ? w1 : w0);
#pragma unroll
                for (int nf = 0; nf < 16; nf++) {
                    float2 bb = *(const float2*)(vbuf + ((kf * 16 + nf) * 32 + lane) * 2);
                    mma_tf32(o[nf], a,
                             __float_as_uint(bb.x), __float_as_uint(bb.y));
                }
            }
        }

        __syncthreads();
        if (kt + 2 < nkt) { stage(kt + 2, buf); CP_COMMIT(); }
    }

    // ---- write output: [b*n, h*a], rna for Wo GEMM ----
    const float il0 = 1.f / l0, il1 = 1.f / l1;
    const int b2 = bh >> 4, h2 = bh & 15;
    float* o0 = O + (size_t)(b2 * N + row0) * HD + h2 * A;
    float* o1 = O + (size_t)(b2 * N + row1) * HD + h2 * A;
#pragma unroll
    for (int nf = 0; nf < 16; nf++) {
        int col = nf * 8 + 2 * tig;
        *(float2*)(o0 + col) = make_float2(rna_tf32(o[nf][0] * il0),
                                           rna_tf32(o[nf][1] * il0));
        *(float2*)(o1 + col) = make_float2(rna_tf32(o[nf][2] * il1),
                                           rna_tf32(o[nf][3] * il1));
    }
}

// ---------------------------------------------------------------------------
extern "C" void kernel_launch(void* const* d_in, const int* in_sizes, int n_in,
                              void* d_out, int out_size) {
    const float* q  = (const float*)d_in[0];
    const float* Wq = (const float*)d_in[1];
    const float* Wk = (const float*)d_in[2];
    const float* Wv = (const float*)d_in[3];
    const float* Wo = (const float*)d_in[4];
    float* out = (float*)d_out;

    float *qr, *Wqr, *Wkr, *Wvr, *Wor, *Qp, *Kp, *Vp, *AOp;
    cudaGetSymbolAddress((void**)&qr,  g_qr);
    cudaGetSymbolAddress((void**)&Wqr, g_Wqr);
    cudaGetSymbolAddress((void**)&Wkr, g_Wkr);
    cudaGetSymbolAddress((void**)&Wvr, g_Wvr);
    cudaGetSymbolAddress((void**)&Wor, g_Wor);
    cudaGetSymbolAddress((void**)&Qp,  g_Q);
    cudaGetSymbolAddress((void**)&Kp,  g_K);
    cudaGetSymbolAddress((void**)&Vp,  g_V);
    cudaGetSymbolAddress((void**)&AOp, g_AO);

    cudaFuncSetAttribute(qkv_gemm, cudaFuncAttributeMaxDynamicSharedMemorySize,
                         GEMM_SMEM);
    cudaFuncSetAttribute(out_gemm, cudaFuncAttributeMaxDynamicSharedMemorySize,
                         GEMM_SMEM);
    cudaFuncSetAttribute(attn_mma_kernel,
                         cudaFuncAttributeMaxDynamicSharedMemorySize, ATTN_SMEM);

    // fused rna pre-pass (q + 4 weights)
    {
        int total = NQ4 + 4 * NW4;   // 6,291,456
        round_all_kernel<<<total / 256, 256>>>(
            (const float4*)q, (const float4*)Wq, (const float4*)Wk,
            (const float4*)Wv, (const float4*)Wo,
            (float4*)qr, (float4*)Wqr, (float4*)Wkr, (float4*)Wvr, (float4*)Wor);
    }

    // fused QKV projections
    qkv_gemm<<<dim3(16, 32, 3), 256, GEMM_SMEM>>>(qr, Wqr, Wkr, Wvr, Qp, Kp, Vp);

    // RoPE on Q and K
    int npairs = B * H * N * (A / 2);
    rope_kernel<<<npairs / 256, 256>>>(Qp, Kp);

    // tensor-core causal flash attention (64q CTAs, 2/SM)
    attn_mma_kernel<<<dim3(N / AQT, B * H), 128, ATTN_SMEM>>>(Qp, Kp, Vp, AOp);

    // output projection
    out_gemm<<<dim3(16, 32), 256, GEMM_SMEM>>>(AOp, Wor, out);
}

// round 8
// speedup vs baseline: 9.6779x; 1.0954x over previous
#include <cuda_runtime.h>
#include <cstdint>
#include <math.h>

// Problem constants
constexpr int B = 2;
constexpr int H = 16;
constexpr int N = 2048;
constexpr int A = 128;           // head dim
constexpr int W = 2048;          // model width
constexpr int HD = H * A;        // 2048
constexpr int Mdim = B * N;      // 4096
constexpr int Kdim = W;          // 2048

// Scratch (device globals — no allocation allowed)
__device__ float g_qr [Mdim * Kdim];     // tf32-rounded q
__device__ float g_Wqr[HD * W];
__device__ float g_Wkr[HD * W];
__device__ float g_Wvr[HD * W];
__device__ float g_Wor[W * HD];
__device__ float g_Q  [B * H * N * A];   // head-major
__device__ float g_K  [B * H * N * A];
__device__ float g_V  [B * H * N * A];
__device__ float g_AO [Mdim * HD];       // [b*n, h*a], rna-rounded by attention

// ---------------------------------------------------------------------------
// helpers
// ---------------------------------------------------------------------------
__device__ __forceinline__ float rna_tf32(float x) {
    uint32_t u;
    asm("cvt.rna.tf32.f32 %0, %1;" : "=r"(u) : "f"(x));
    return __uint_as_float(u);
}
__device__ __forceinline__ uint32_t rna_tf32_bits(float x) {
    uint32_t u;
    asm("cvt.rna.tf32.f32 %0, %1;" : "=r"(u) : "f"(x));
    return u;
}
__device__ __forceinline__ float ex2f(float x) {
    float y;
    asm("ex2.approx.ftz.f32 %0, %1;" : "=f"(y) : "f"(x));
    return y;
}
__device__ __forceinline__ uint32_t smem_u32(const void* p) {
    uint32_t a;
    asm("{ .reg .u64 t; cvta.to.shared.u64 t, %1; cvt.u32.u64 %0, t; }"
        : "=r"(a) : "l"(p));
    return a;
}
__device__ __forceinline__ void mma_tf32(float* c, const uint32_t* a,
                                         uint32_t b0, uint32_t b1) {
    asm volatile(
        "mma.sync.aligned.m16n8k8.row.col.f32.tf32.tf32.f32 "
        "{%0,%1,%2,%3}, {%4,%5,%6,%7}, {%8,%9}, {%0,%1,%2,%3};"
        : "+f"(c[0]), "+f"(c[1]), "+f"(c[2]), "+f"(c[3])
        : "r"(a[0]), "r"(a[1]), "r"(a[2]), "r"(a[3]), "r"(b0), "r"(b1));
}
__device__ __forceinline__ void ldsm_x4(uint32_t* r, uint32_t addr) {
    asm volatile("ldmatrix.sync.aligned.m8n8.x4.shared.b16 {%0,%1,%2,%3}, [%4];"
                 : "=r"(r[0]), "=r"(r[1]), "=r"(r[2]), "=r"(r[3]) : "r"(addr));
}
#define CP_ASYNC4(dst, src) \
    asm volatile("cp.async.ca.shared.global [%0], [%1], 4;" :: "r"(dst), "l"(src))
#define CP_ASYNC16(dst, src) \
    asm volatile("cp.async.cg.shared.global [%0], [%1], 16;" :: "r"(dst), "l"(src))
#define CP_COMMIT() asm volatile("cp.async.commit_group;" ::: "memory")
#define CP_WAIT(n)  asm volatile("cp.async.wait_group %0;" :: "n"(n) : "memory")

// ---------------------------------------------------------------------------
// Fused rna-rounding pre-pass over q + 4 weights (single DRAM-bound launch).
// ---------------------------------------------------------------------------
constexpr int NQ4 = Mdim * Kdim / 4;   // 2,097,152
constexpr int NW4 = HD * W / 4;        // 1,048,576 = 2^20

__global__ void round_all_kernel(const float4* __restrict__ q,
                                 const float4* __restrict__ wq,
                                 const float4* __restrict__ wk,
                                 const float4* __restrict__ wv,
                                 const float4* __restrict__ wo,
                                 float4* __restrict__ qr,
                                 float4* __restrict__ wqr,
                                 float4* __restrict__ wkr,
                                 float4* __restrict__ wvr,
                                 float4* __restrict__ wor) {
    int i = blockIdx.x * blockDim.x + threadIdx.x;
    const float4* src;
    float4* dst;
    int off;
    if (i < NQ4) {
        src = q; dst = qr; off = i;
    } else {
        int j = i - NQ4;
        int w = j >> 20;
        off = j & (NW4 - 1);
        src = (w == 0) ? wq : (w == 1) ? wk : (w == 2) ? wv : wo;
        dst = (w == 0) ? wqr : (w == 1) ? wkr : (w == 2) ? wvr : wor;
    }
    float4 v = src[off];
    v.x = rna_tf32(v.x); v.y = rna_tf32(v.y);
    v.z = rna_tf32(v.z); v.w = rna_tf32(v.w);
    dst[off] = v;
}

// ---------------------------------------------------------------------------
// tf32 mma.sync GEMM v2: 128x128 CTA, BK=32, 128 threads, 4 warps of 64x64.
// 3-stage cp.async pipeline, XOR-swizzled row-major smem, ldmatrix.x4.
// Warp 64x64 halves fragment traffic per MMA vs 32x64.
// ---------------------------------------------------------------------------
constexpr int TILE_B     = 128 * 32 * 4;          // 16384 per operand
constexpr int STAGE_B    = 2 * TILE_B;            // 32768
constexpr int GEMM_SMEM  = 3 * STAGE_B;           // 98304

template <int SCATTER_C>
__device__ __forceinline__ void gemm_body(const float* __restrict__ Ag,
                                          const float* __restrict__ Bg,
                                          float* __restrict__ Cg) {
    extern __shared__ float gs[];
    const uint32_t sbase = smem_u32(gs);
    const int tid  = threadIdx.x;
    const int lane = tid & 31;
    const int wid  = tid >> 5;      // 0..3
    const int wm   = wid & 1;       // 64 rows each
    const int wn   = wid >> 1;      // 64 cols each
    const int m0   = blockIdx.y * 128;
    const int n0   = blockIdx.x * 128;

    float c[4][8][4];
#pragma unroll
    for (int mi = 0; mi < 4; mi++)
#pragma unroll
        for (int ni = 0; ni < 8; ni++)
#pragma unroll
            for (int j = 0; j < 4; j++) c[mi][ni][j] = 0.f;

    const int srow0 = tid >> 3;     // 0..15
    const int sc16  = tid & 7;
    auto stage = [&](int kt, int slot) {
        const uint32_t base = sbase + slot * STAGE_B;
        const float* Asrc = Ag + (size_t)(m0 + srow0) * Kdim + kt * 32 + sc16 * 4;
        const float* Bsrc = Bg + (size_t)(n0 + srow0) * Kdim + kt * 32 + sc16 * 4;
#pragma unroll
        for (int i = 0; i < 8; i++) {
            int row = srow0 + i * 16;
            uint32_t off = (uint32_t)row * 128 + ((sc16 ^ (row & 7)) << 4);
            CP_ASYNC16(base + off,          Asrc + (size_t)i * 16 * Kdim);
            CP_ASYNC16(base + TILE_B + off, Bsrc + (size_t)i * 16 * Kdim);
        }
    };

    const int a_row = wm * 64 + (lane & 15);
    const int a_hi  = lane >> 4;
    const int b_row = wn * 64 + (lane & 7) + ((lane >> 4) << 3);
    const int b_hi  = (lane >> 3) & 1;

    stage(0, 0); CP_COMMIT();
    stage(1, 1); CP_COMMIT();

    constexpr int NKT = Kdim / 32;
    int slot = 0;
    for (int kt = 0; kt < NKT; kt++) {
        CP_WAIT(1);
        __syncthreads();
        if (kt + 2 < NKT) {
            int ns = slot + 2; if (ns >= 3) ns -= 3;
            stage(kt + 2, ns);
        }
        CP_COMMIT();

        const uint32_t abase = sbase + slot * STAGE_B;
        const uint32_t bbase = abase + TILE_B;
#pragma unroll
        for (int ks = 0; ks < 4; ks++) {
            uint32_t af[4][4];
#pragma unroll
            for (int mi = 0; mi < 4; mi++) {
                int row = a_row + mi * 16;
                uint32_t addr = abase + (uint32_t)row * 128
                              + (((ks * 2 + a_hi) ^ (row & 7)) << 4);
                ldsm_x4(af[mi], addr);
            }
#pragma unroll
            for (int nip = 0; nip < 4; nip++) {
                int row = b_row + nip * 16;
                uint32_t addr = bbase + (uint32_t)row * 128
                              + (((ks * 2 + b_hi) ^ (row & 7)) << 4);
                uint32_t bf[4];
                ldsm_x4(bf, addr);
#pragma unroll
                for (int mi = 0; mi < 4; mi++) {
                    mma_tf32(c[mi][2 * nip],     af[mi], bf[0], bf[1]);
                    mma_tf32(c[mi][2 * nip + 1], af[mi], bf[2], bf[3]);
                }
            }
        }
        slot++; if (slot >= 3) slot = 0;
    }

    const int gid = lane >> 2, tig = lane & 3;
#pragma unroll
    for (int mi = 0; mi < 4; mi++) {
#pragma unroll
        for (int ni = 0; ni < 8; ni++) {
            int n = n0 + wn * 64 + ni * 8 + tig * 2;
#pragma unroll
            for (int half = 0; half < 2; half++) {
                int m = m0 + wm * 64 + mi * 16 + gid + half * 8;
                float2 v = make_float2(c[mi][ni][half * 2], c[mi][ni][half * 2 + 1]);
                size_t dst;
                if (SCATTER_C) {
                    int b2 = m >> 11, np = m & 2047, h2 = n >> 7, a0 = n & 127;
                    dst = ((((size_t)b2 * H + h2) * N) + np) * A + a0;
                } else {
                    dst = (size_t)m * 2048 + n;
                }
                *(float2*)(Cg + dst) = v;
            }
        }
    }
}

__global__ __launch_bounds__(128, 2)
void qkv_gemm(const float* __restrict__ q,
              const float* __restrict__ Wq, const float* __restrict__ Wk,
              const float* __restrict__ Wv,
              float* __restrict__ Qp, float* __restrict__ Kp,
              float* __restrict__ Vp) {
    const int z = blockIdx.z;
    const float* Bg = (z == 0) ? Wq : (z == 1) ? Wk : Wv;
    float*       Cg = (z == 0) ? Qp : (z == 1) ? Kp : Vp;
    gemm_body<1>(q, Bg, Cg);
}

__global__ __launch_bounds__(128, 2)
void out_gemm(const float* __restrict__ Ag, const float* __restrict__ Bg,
              float* __restrict__ Cg) {
    gemm_body<0>(Ag, Bg, Cg);
}

// ---------------------------------------------------------------------------
// RoPE (interleaved pairs), in place on Q and K (head-major layout).
// ---------------------------------------------------------------------------
__global__ void rope_kernel(float* __restrict__ Q, float* __restrict__ K) {
    int idx = blockIdx.x * blockDim.x + threadIdx.x;
    int i = idx & 63;
    int npos = (idx >> 6) & 2047;
    float freq = __powf(10000.0f, -(float)i * (1.0f / 63.0f));
    float th = (float)npos * freq;
    float s, c;
    sincosf(th, &s, &c);
    size_t base = (size_t)idx * 2;

    float q0 = Q[base], q1 = Q[base + 1];
    Q[base]     = q0 * c - q1 * s;
    Q[base + 1] = q1 * c + q0 * s;

    float k0 = K[base], k1 = K[base + 1];
    K[base]     = k0 * c - k1 * s;
    K[base + 1] = k1 * c + k0 * s;
}

// ---------------------------------------------------------------------------
// Tensor-core causal flash attention v3.
// CTA: 64 queries, 128 threads (4 warps x 16 q rows), 32-key tiles, 2-stage.
// Changes vs v2: split S accumulators (8-way MMA ILP), log2e folded into
// Q scale + raw ex2, V smem re-laid for conflict-free lds.128.
// ---------------------------------------------------------------------------
constexpr int AQT = 64;
constexpr int AKT = 32;
constexpr int K_TILE_B  = AKT * 128 * 4;          // 16384 B
constexpr int STAGE_F   = AKT * 128 * 2;          // 8192 floats (K + V)
constexpr int ATTN_SMEM = 2 * STAGE_F * 4;        // 65536 B

__global__ __launch_bounds__(128)
void attn_mma_kernel(const float* __restrict__ Q, const float* __restrict__ K,
                     const float* __restrict__ V, float* __restrict__ O) {
    extern __shared__ float smx[];
    const uint32_t sbase = smem_u32(smx);

    const int tid  = threadIdx.x;
    const int lane = tid & 31;
    const int wid  = tid >> 5;          // 0..3
    const int gid  = lane >> 2, tig = lane & 3;
    const int bh   = blockIdx.y;
    const int qt   = gridDim.x - 1 - blockIdx.x;   // heavy tiles first
    const int q0   = qt * AQT;

    const float* Qb = Q + (size_t)bh * N * A;
    const float* Kb = K + (size_t)bh * N * A;
    const float* Vb = V + (size_t)bh * N * A;

    // ---- stage Q (64 rows x 512B) row-major swizzled into stage-0 alias ----
    {
        const int c16 = tid & 31;
        const int r0  = tid >> 5;       // 0..3
#pragma unroll
        for (int i = 0; i < 16; i++) {
            int row = r0 + i * 4;
            uint32_t off = (uint32_t)row * 512 + ((c16 ^ (row & 7)) << 4);
            CP_ASYNC16(sbase + off, Qb + (size_t)(q0 + row) * A + c16 * 4);
        }
        CP_COMMIT();
        CP_WAIT(0);
        __syncthreads();
    }

    // ---- Q A-frags -> registers; fold 1/sqrt(128) * log2(e) into scale ----
    const float scl = 0.08838834764831845f * 1.4426950408889634f;
    uint32_t qf[16][4];
    {
        const int a_row = wid * 16 + (lane & 15);
        const int a_hi  = lane >> 4;
#pragma unroll
        for (int kd = 0; kd < 16; kd++) {
            uint32_t addr = sbase + (uint32_t)a_row * 512
                          + (((kd * 2 + a_hi) ^ (a_row & 7)) << 4);
            ldsm_x4(qf[kd], addr);
#pragma unroll
            for (int j = 0; j < 4; j++)
                qf[kd][j] = rna_tf32_bits(__uint_as_float(qf[kd][j]) * scl);
        }
    }
    __syncthreads();   // Q smem now reusable as KV stage 0

    // ---- KV staging ----
    const int s_c16 = tid & 31;
    const int s_r0  = tid >> 5;
    // V layout: [kf][lane][chunk^ (lane&7)][pos]   (32 floats per lane row)
    const int v_d7  = (tid & 7) * 4;       // (d&7)*4
    const int v_pos = ((tid >> 3) & 1) * 2;
    const int v_chk = tid >> 4;            // d>>4
    auto stage = [&](int kt, int slot) {
        const uint32_t kb = sbase + slot * (STAGE_F * 4);
        const uint32_t vb = kb + K_TILE_B;
        const float* Kg = Kb + (size_t)(kt * AKT) * A;
        const float* Vg = Vb + (size_t)(kt * AKT) * A + tid;   // column d=tid
#pragma unroll
        for (int i = 0; i < 8; i++) {
            int row = s_r0 + i * 4;
            uint32_t off = (uint32_t)row * 512 + ((s_c16 ^ (row & 7)) << 4);
            CP_ASYNC16(kb + off, Kg + (size_t)row * A + s_c16 * 4);
        }
#pragma unroll
        for (int key = 0; key < 32; key++) {
            int kf    = key >> 3;
            int lanev = v_d7 + (key & 3);
            int chunk = v_chk ^ (lanev & 7);
            int pos   = v_pos + ((key >> 2) & 1);
            uint32_t va = vb + ((((kf * 32 + lanev) * 32) + chunk * 4 + pos) << 2);
            CP_ASYNC4(va, Vg + (size_t)key * A);
        }
    };

    const int nkt  = 2 * qt + 2;                 // 32-key tiles (CTA)
    const int nktw = 2 * qt + (wid >> 1) + 1;    // this warp's tiles

    float o[16][4];
#pragma unroll
    for (int nf = 0; nf < 16; nf++)
#pragma unroll
        for (int j = 0; j < 4; j++) o[nf][j] = 0.f;
    float m0 = -1e30f, m1 = -1e30f, l0 = 0.f, l1 = 0.f;

    const int row0 = q0 + wid * 16 + gid;
    const int row1 = row0 + 8;
    const int b_row = (lane & 7) + ((lane >> 4) << 3);   // 0..15
    const int b_hi  = (lane >> 3) & 1;

    stage(0, 0); CP_COMMIT();
    stage(1, 1); CP_COMMIT();

    for (int kt = 0; kt < nkt; kt++) {
        const int buf = kt & 1;
        if (kt < nkt - 1) { CP_WAIT(1); } else { CP_WAIT(0); }
        __syncthreads();

        if (kt < nktw) {
            const uint32_t kbase = sbase + buf * (STAGE_F * 4);
            const float*   vbuf  = smx + buf * STAGE_F + AKT * 128;

            // ---- S = Q K^T : split even/odd-kd accumulators (8-way ILP) ----
            float s2[2][4][4];
#pragma unroll
            for (int p = 0; p < 2; p++)
#pragma unroll
                for (int nk = 0; nk < 4; nk++)
#pragma unroll
                    for (int j = 0; j < 4; j++) s2[p][nk][j] = 0.f;

#pragma unroll
            for (int kd = 0; kd < 16; kd++) {
                float* sp = &s2[kd & 1][0][0];
                uint32_t col = ((kd * 2 + b_hi) ^ (b_row & 7)) << 4;
                uint32_t bf0[4], bf1[4];
                ldsm_x4(bf0, kbase + (uint32_t)b_row * 512 + col);
                ldsm_x4(bf1, kbase + (uint32_t)(b_row + 16) * 512 + col);
                mma_tf32(sp + 0,  qf[kd], bf0[0], bf0[1]);
                mma_tf32(sp + 4,  qf[kd], bf0[2], bf0[3]);
                mma_tf32(sp + 8,  qf[kd], bf1[0], bf1[1]);
                mma_tf32(sp + 12, qf[kd], bf1[2], bf1[3]);
            }
            float s[4][4];
#pragma unroll
            for (int nk = 0; nk < 4; nk++)
#pragma unroll
                for (int j = 0; j < 4; j++)
                    s[nk][j] = s2[0][nk][j] + s2[1][nk][j];

            // ---- causal mask (diagonal tile only) ----
            if (kt == nktw - 1) {
                int colb = kt * AKT + 2 * tig;
#pragma unroll
                for (int nk = 0; nk < 4; nk++) {
                    int c0 = colb + nk * 8;
                    if (c0     > row0) s[nk][0] = -1e30f;
                    if (c0 + 1 > row0) s[nk][1] = -1e30f;
                    if (c0     > row1) s[nk][2] = -1e30f;
                    if (c0 + 1 > row1) s[nk][3] = -1e30f;
                }
            }

            // ---- online softmax (log2 domain) ----
            float mx0 = -1e30f, mx1 = -1e30f;
#pragma unroll
            for (int nk = 0; nk < 4; nk++) {
                mx0 = fmaxf(mx0, fmaxf(s[nk][0], s[nk][1]));
                mx1 = fmaxf(mx1, fmaxf(s[nk][2], s[nk][3]));
            }
            mx0 = fmaxf(mx0, __shfl_xor_sync(0xffffffffu, mx0, 1));
            mx0 = fmaxf(mx0, __shfl_xor_sync(0xffffffffu, mx0, 2));
            mx1 = fmaxf(mx1, __shfl_xor_sync(0xffffffffu, mx1, 1));
            mx1 = fmaxf(mx1, __shfl_xor_sync(0xffffffffu, mx1, 2));
            float mn0 = fmaxf(m0, mx0), mn1 = fmaxf(m1, mx1);
            float cor0 = ex2f(m0 - mn0), cor1 = ex2f(m1 - mn1);
            m0 = mn0; m1 = mn1;

            float rs0 = 0.f, rs1 = 0.f;
#pragma unroll
            for (int nk = 0; nk < 4; nk++) {
                s[nk][0] = ex2f(s[nk][0] - mn0);
                s[nk][1] = ex2f(s[nk][1] - mn0);
                s[nk][2] = ex2f(s[nk][2] - mn1);
                s[nk][3] = ex2f(s[nk][3] - mn1);
                rs0 += s[nk][0] + s[nk][1];
                rs1 += s[nk][2] + s[nk][3];
            }
            rs0 += __shfl_xor_sync(0xffffffffu, rs0, 1);
            rs0 += __shfl_xor_sync(0xffffffffu, rs0, 2);
            rs1 += __shfl_xor_sync(0xffffffffu, rs1, 1);
            rs1 += __shfl_xor_sync(0xffffffffu, rs1, 2);
            l0 = l0 * cor0 + rs0;
            l1 = l1 * cor1 + rs1;

#pragma unroll
            for (int nf = 0; nf < 16; nf++) {
                o[nf][0] *= cor0; o[nf][1] *= cor0;
                o[nf][2] *= cor1; o[nf][3] *= cor1;
            }

            // ---- O += P V : P C-layout -> A-frag via quad shuffles ----
            const int lA = (gid << 2) + (tig >> 1);
            const int lB = lA + 2;
            const bool odd = tig & 1;
            const float* vrow = vbuf + (uint32_t)lane * 32;
            const int ln7 = (lane & 7);
#pragma unroll
            for (int kf = 0; kf < 4; kf++) {
                float p0 = s[kf][0], p1 = s[kf][1], p2 = s[kf][2], p3 = s[kf][3];
                float x0 = __shfl_sync(0xffffffffu, p0, lA);
                float x1 = __shfl_sync(0xffffffffu, p1, lA);
                float y0 = __shfl_sync(0xffffffffu, p0, lB);
                float y1 = __shfl_sync(0xffffffffu, p1, lB);
                float z0 = __shfl_sync(0xffffffffu, p2, lA);
                float z1 = __shfl_sync(0xffffffffu, p3, lA);
                float w0 = __shfl_sync(0xffffffffu, p2, lB);
                float w1 = __shfl_sync(0xffffffffu, p3, lB);
                uint32_t a[4];
                a[0] = rna_tf32_bits(odd ? x1 : x0);
                a[1] = rna_tf32_bits(odd ? z1 : z0);
                a[2] = rna_tf32_bits(odd ? y1 : y0);
                a[3] = rna_tf32_bits(odd ? w1 : w0);
                const float* vk = vrow + kf * 32 * 32;
#pragma unroll
                for (int j2 = 0; j2 < 8; j2++) {
                    float4 vv = *(const float4*)(vk + ((j2 ^ ln7) << 2));
                    mma_tf32(o[2 * j2],     a, __float_as_uint(vv.x),
                                               __float_as_uint(vv.y));
                    mma_tf32(o[2 * j2 + 1], a, __float_as_uint(vv.z),
                                               __float_as_uint(vv.w));
                }
            }
        }

        __syncthreads();
        if (kt + 2 < nkt) { stage(kt + 2, buf); CP_COMMIT(); }
    }

    // ---- write output: [b*n, h*a], rna for Wo GEMM ----
    const float il0 = 1.f / l0, il1 = 1.f / l1;
    const int b2 = bh >> 4, h2 = bh & 15;
    float* o0 = O + (size_t)(b2 * N + row0) * HD + h2 * A;
    float* o1 = O + (size_t)(b2 * N + row1) * HD + h2 * A;
#pragma unroll
    for (int nf = 0; nf < 16; nf++) {
        int col = nf * 8 + 2 * tig;
        *(float2*)(o0 + col) = make_float2(rna_tf32(o[nf][0] * il0),
                                           rna_tf32(o[nf][1] * il0));
        *(float2*)(o1 + col) = make_float2(rna_tf32(o[nf][2] * il1),
                                           rna_tf32(o[nf][3] * il1));
    }
}

// ---------------------------------------------------------------------------
extern "C" void kernel_launch(void* const* d_in, const int* in_sizes, int n_in,
                              void* d_out, int out_size) {
    const float* q  = (const float*)d_in[0];
    const float* Wq = (const float*)d_in[1];
    const float* Wk = (const float*)d_in[2];
    const float* Wv = (const float*)d_in[3];
    const float* Wo = (const float*)d_in[4];
    float* out = (float*)d_out;

    float *qr, *Wqr, *Wkr, *Wvr, *Wor, *Qp, *Kp, *Vp, *AOp;
    cudaGetSymbolAddress((void**)&qr,  g_qr);
    cudaGetSymbolAddress((void**)&Wqr, g_Wqr);
    cudaGetSymbolAddress((void**)&Wkr, g_Wkr);
    cudaGetSymbolAddress((void**)&Wvr, g_Wvr);
    cudaGetSymbolAddress((void**)&Wor, g_Wor);
    cudaGetSymbolAddress((void**)&Qp,  g_Q);
    cudaGetSymbolAddress((void**)&Kp,  g_K);
    cudaGetSymbolAddress((void**)&Vp,  g_V);
    cudaGetSymbolAddress((void**)&AOp, g_AO);

    cudaFuncSetAttribute(qkv_gemm, cudaFuncAttributeMaxDynamicSharedMemorySize,
                         GEMM_SMEM);
    cudaFuncSetAttribute(out_gemm, cudaFuncAttributeMaxDynamicSharedMemorySize,
                         GEMM_SMEM);
    cudaFuncSetAttribute(attn_mma_kernel,
                         cudaFuncAttributeMaxDynamicSharedMemorySize, ATTN_SMEM);

    // fused rna pre-pass (q + 4 weights)
    {
        int total = NQ4 + 4 * NW4;   // 6,291,456
        round_all_kernel<<<total / 256, 256>>>(
            (const float4*)q, (const float4*)Wq, (const float4*)Wk,
            (const float4*)Wv, (const float4*)Wo,
            (float4*)qr, (float4*)Wqr, (float4*)Wkr, (float4*)Wvr, (float4*)Wor);
    }

    // fused QKV projections (64x64 warp tiles)
    qkv_gemm<<<dim3(16, 32, 3), 128, GEMM_SMEM>>>(qr, Wqr, Wkr, Wvr, Qp, Kp, Vp);

    // RoPE on Q and K
    int npairs = B * H * N * (A / 2);
    rope_kernel<<<npairs / 256, 256>>>(Qp, Kp);

    // tensor-core causal flash attention
    attn_mma_kernel<<<dim3(N / AQT, B * H), 128, ATTN_SMEM>>>(Qp, Kp, Vp, AOp);

    // output projection
    out_gemm<<<dim3(16, 32), 128, GEMM_SMEM>>>(AOp, Wor, out);
}